// round 11
// baseline (speedup 1.0000x reference)
#include <cuda_runtime.h>
#include <cuda_bf16.h>
#include <math.h>

#define BATCH 2
#define N1 4096
#define N2 4096
#define DD 64
#define KN 16
#define KCC 8
#define CP 80      // padded feature channels (67 / 70 used)
#define CO 128

// ---------------- scratch (static device memory; no runtime alloc) ----------------
__device__ float g_dist[(size_t)BATCH * N1 * N2];        // 134 MB
__device__ float g_F1[BATCH * CP * N1];
__device__ float g_F2[BATCH * CP * N2];
__device__ float g_CB[BATCH * CP * N1];
__device__ float g_nA[BATCH * N1];
__device__ float g_nB[BATCH * N2];
__device__ float g_nC[BATCH * N1];
__device__ int   g_idx1[BATCH * N1 * KN];
__device__ int   g_idx2[BATCH * N1 * KN];
__device__ float g_vw[BATCH * N1 * 3];
__device__ float g_wf[BATCH * N1];
__device__ float g_wr[BATCH * N1];
__device__ float g_p1T[BATCH * N1 * DD];
__device__ float g_p2T[BATCH * N2 * DD];
__device__ float g_x1T[BATCH * N1 * 3];
__device__ float g_x2T[BATCH * N2 * 3];
__device__ float g_p2p[(size_t)BATCH * N1 * CO];
__device__ uint2 g_wbf[3][72][128];     // bf16 hi/lo split, transposed MLP weights (k-pairs)

__device__ __forceinline__ float leakyf(float x) { return x >= 0.f ? x : 0.1f * x; }
__device__ __forceinline__ unsigned long long u64min(unsigned long long a, unsigned long long b) {
    return a < b ? a : b;
}

// ---- tf32 helpers (dist kernel) ----
__device__ __forceinline__ float f2tf32f(float x) {
    unsigned int r;
    asm("cvt.rna.tf32.f32 %0, %1;" : "=r"(r) : "f"(x));
    return __uint_as_float(r);
}

#define MMA_TF32(acc, A0, A1, A2, A3, B0, B1)                                   \
    asm volatile("mma.sync.aligned.m16n8k8.row.col.f32.tf32.tf32.f32 "          \
                 "{%0,%1,%2,%3}, {%4,%5,%6,%7}, {%8,%9}, {%0,%1,%2,%3};"        \
                 : "+f"(acc[0]), "+f"(acc[1]), "+f"(acc[2]), "+f"(acc[3])       \
                 : "r"(__float_as_uint(A0)), "r"(__float_as_uint(A1)),          \
                   "r"(__float_as_uint(A2)), "r"(__float_as_uint(A3)),          \
                   "r"(__float_as_uint(B0)), "r"(__float_as_uint(B1)))

// ---- bf16 helpers (mlp kernel) ----
__device__ __forceinline__ float bf16_trunc(float x) {          // exact split: top 16 bits
    return __uint_as_float(__float_as_uint(x) & 0xffff0000u);
}
__device__ __forceinline__ unsigned packbf2(float lo_elem, float hi_elem) {
    __nv_bfloat162 v = __floats2bfloat162_rn(lo_elem, hi_elem); // .x = first arg (low half)
    return *(unsigned*)&v;
}

#define MMA_BF16(acc, A0, A1, A2, A3, B0, B1)                                   \
    asm volatile("mma.sync.aligned.m16n8k16.row.col.f32.bf16.bf16.f32 "         \
                 "{%0,%1,%2,%3}, {%4,%5,%6,%7}, {%8,%9}, {%0,%1,%2,%3};"        \
                 : "+f"(acc[0]), "+f"(acc[1]), "+f"(acc[2]), "+f"(acc[3])       \
                 : "r"(A0), "r"(A1), "r"(A2), "r"(A3), "r"(B0), "r"(B1))

// ---------------- rigid 3x3 least squares + mask ----------------
__global__ void k_rigid(const float* __restrict__ xyz1, const float* __restrict__ vel1,
                        const float* __restrict__ fcc, const float* __restrict__ fcv,
                        float* __restrict__ out_vw)
{
    int t = blockIdx.x * blockDim.x + threadIdx.x;
    if (t >= BATCH * N1) return;
    int b = t / N1, n = t % N1;
    const float* cc = fcc + (size_t)t * KCC * 3;
    const float* cv = fcv + (size_t)t * KCC;
    double A00 = 1e-6, A01 = 0, A02 = 0, A11 = 1e-6, A12 = 0, A22 = 1e-6;
    double r0 = 0, r1 = 0, r2 = 0;
    for (int k = 0; k < KCC; k++) {
        double x = cc[k * 3 + 0], y = cc[k * 3 + 1], z = cc[k * 3 + 2];
        double inv = 1.0 / sqrt(x * x + y * y + z * z);
        x *= inv; y *= inv; z *= inv;
        A00 += x * x; A01 += x * y; A02 += x * z;
        A11 += y * y; A12 += y * z; A22 += z * z;
        double v = (double)cv[k];
        r0 += x * v; r1 += y * v; r2 += z * v;
    }
    double c00 = A11 * A22 - A12 * A12;
    double c01 = A01 * A22 - A12 * A02;
    double c02 = A01 * A12 - A11 * A02;
    double det = A00 * c00 - A01 * c01 + A02 * c02;
    double id = 1.0 / det;
    double v0 = (r0 * c00 - A01 * (r1 * A22 - A12 * r2) + A02 * (r1 * A12 - A11 * r2)) * id;
    double v1 = (A00 * (r1 * A22 - A12 * r2) - r0 * c01 + A02 * (A01 * r2 - r1 * A02)) * id;
    double v2 = (A00 * (A11 * r2 - r1 * A12) - A01 * (A01 * r2 - r1 * A02) + r0 * c02) * id;

    float fx = xyz1[(b * 3 + 0) * N1 + n];
    float fy = xyz1[(b * 3 + 1) * N1 + n];
    float fz = xyz1[(b * 3 + 2) * N1 + n];
    double inl = 1.0 / sqrt((double)fx * fx + (double)fy * fy + (double)fz * fz);
    double err = fabs((v0 * fx + v1 * fy + v2 * fz) * inl - (double)vel1[t]);
    bool m = (err <= 5.0);
    g_wf[t] = m ? 0.1f : 0.9f;
    g_wr[t] = m ? 0.9f : 0.1f;
    g_vw[t * 3 + 0] = (float)v0;
    g_vw[t * 3 + 1] = (float)v1;
    g_vw[t * 3 + 2] = (float)v2;
    if (out_vw) {
        out_vw[t * 3 + 0] = (float)v0;
        out_vw[t * 3 + 1] = (float)v1;
        out_vw[t * 3 + 2] = (float)v2;
    }
}

// ---------------- fused: weighted feature build + xyz transposes ----------------
__global__ void k_prep(const float* __restrict__ xyz1, const float* __restrict__ xyz2,
                       const float* __restrict__ pts1, const float* __restrict__ pts2,
                       const float* __restrict__ wxyz_p, const float* __restrict__ wpts_p)
{
    float wx = *wxyz_p, wp = *wpts_p;
    const int totalF = BATCH * CP * N1;
    const int tx3 = BATCH * 3 * N1;
    const int total = 2 * totalF + 2 * tx3;
    for (int e = blockIdx.x * blockDim.x + threadIdx.x; e < total;
         e += gridDim.x * blockDim.x) {
        if (e < 2 * totalF) {
            int which = e / totalF;
            int r = e % totalF;
            int b = r / (CP * N1);
            int c = (r / N1) % CP;
            int n = r % N1;
            const float* xyz = which ? xyz2 : xyz1;
            const float* pts = which ? pts2 : pts1;
            float* F = which ? g_F2 : g_F1;
            float v = 0.f;
            if (c < 3) v = wx * xyz[(b * 3 + c) * N1 + n];
            else if (c < 67) v = wp * pts[(b * DD + (c - 3)) * N1 + n];
            F[r] = v;
        } else {
            int r = e - 2 * totalF;
            if (r < tx3) {
                int b = r / (3 * N1), c = (r / N1) % 3, n = r % N1;
                g_x1T[(b * N1 + n) * 3 + c] = xyz1[r];
            } else {
                r -= tx3;
                int b = r / (3 * N1), c = (r / N1) % 3, n = r % N1;
                g_x2T[(b * N2 + n) * 3 + c] = xyz2[r];
            }
        }
    }
}

// ---------------- MLP weight transpose + bf16 hi/lo split (runs once) ----------------
__global__ void k_wprep(const float* __restrict__ w0, const float* __restrict__ w1,
                        const float* __restrict__ w2)
{
    const int per = 72 * 128;
    for (int e = blockIdx.x * blockDim.x + threadIdx.x; e < 3 * per;
         e += gridDim.x * blockDim.x) {
        int l = e / per;
        int r = e % per;
        int kp = r >> 7, c = r & 127;
        int KD = (l == 0) ? 131 : 128;
        const float* w = (l == 0) ? w0 : (l == 1) ? w1 : w2;
        int k0 = 2 * kp, k1 = 2 * kp + 1;
        float v0 = (k0 < KD) ? w[c * KD + k0] : 0.f;
        float v1 = (k1 < KD) ? w[c * KD + k1] : 0.f;
        float h0 = bf16_trunc(v0), h1 = bf16_trunc(v1);
        uint2 o;
        o.x = packbf2(h0, h1);
        o.y = packbf2(v0 - h0, v1 - h1);
        g_wbf[l][kp][c] = o;
    }
}

// ---------------- coalesced tiled transpose: [B][C][N] -> [B][N][C], C=64 ----------------
__global__ void __launch_bounds__(256) k_transp(const float* __restrict__ src1,
                                                const float* __restrict__ src2)
{
    __shared__ float t[32][33];
    int zc = blockIdx.y;
    int ct = zc & 1;
    int b = (zc >> 1) & (BATCH - 1);
    int which = zc >> 2;
    const float* src = which ? src2 : src1;
    float* dst = which ? g_p2T : g_p1T;
    int n0 = blockIdx.x * 32;
    int c0 = ct * 32;
    int lx = threadIdx.x & 31, ly = threadIdx.x >> 5;
    #pragma unroll
    for (int r = 0; r < 4; r++) {
        int c = c0 + ly + r * 8;
        t[ly + r * 8][lx] = src[((size_t)b * DD + c) * N1 + n0 + lx];
    }
    __syncthreads();
    #pragma unroll
    for (int r = 0; r < 4; r++) {
        int n = n0 + ly + r * 8;
        dst[((size_t)b * N1 + n) * DD + c0 + lx] = t[lx][ly + r * 8];
    }
}

// ---------------- squared norms of F1/F2 (no rigid dependency) ----------------
__global__ void k_normsAB()
{
    int t = blockIdx.x * blockDim.x + threadIdx.x;
    if (t >= BATCH * 4096) return;
    int b = t / 4096, n = t % 4096;
    float sA = 0.f, sB = 0.f;
    #pragma unroll 8
    for (int c = 0; c < CP; c++) {
        float a = g_F1[(b * CP + c) * 4096 + n];
        float bb = g_F2[(b * CP + c) * 4096 + n];
        sA += a * a;
        sB += bb * bb;
    }
    g_nA[t] = sA;
    g_nB[t] = sB;
}

// ---------------- comb norm (needs rigid + normsAB) ----------------
__global__ void k_nc()
{
    int t = blockIdx.x * blockDim.x + threadIdx.x;
    if (t >= BATCH * N1) return;
    float wf = g_wf[t], wr = g_wr[t];
    float v0 = g_vw[t * 3 + 0], v1 = g_vw[t * 3 + 1], v2 = g_vw[t * 3 + 2];
    g_nC[t] = wf * wf * g_nA[t] + wr * wr * (v0 * v0 + v1 * v1 + v2 * v2);
}

// ---------------- comb features for second KNN ----------------
__global__ void k_comb()
{
    const int total = BATCH * CP * N1;
    for (int e = blockIdx.x * blockDim.x + threadIdx.x; e < total;
         e += gridDim.x * blockDim.x) {
        int b = e / (CP * N1);
        int c = (e / N1) % CP;
        int n = e % N1;
        float v = 0.f;
        if (c < 67) v = g_wf[b * N1 + n] * g_F1[e];
        else if (c < 70) v = g_wr[b * N1 + n] * g_vw[(b * N1 + n) * 3 + (c - 67)];
        g_CB[e] = v;
    }
}

// ---------------- distance GEMM on tensor cores (3xTF32, hi/lo interleaved) ----------------
#define CPK 16
#define S2 132
#define SLAB2 (CPK * S2)
#define DIST_SMEM ((2 * SLAB2 * 2 + 256) * 4)

__global__ void __launch_bounds__(256) k_dist_tc(int sel)
{
    extern __shared__ float2 dsm2[];
    float2* As2 = dsm2;                 // [CPK][S2] (hi,lo)
    float2* Bs2 = As2 + SLAB2;
    float* nAs = (float*)(Bs2 + SLAB2); // 128
    float* nBs = nAs + 128;             // 128

    const float* FA = sel ? g_CB : g_F1;
    const float* FB = sel ? g_CB : g_F2;
    const float* nAv = sel ? g_nC : g_nA;
    const float* nBv = sel ? g_nC : g_nB;

    int b = blockIdx.z;
    int i0 = blockIdx.y * 128, j0 = blockIdx.x * 128;
    const float* Asrc = FA + (size_t)b * CP * N1 + i0;
    const float* Bsrc = FB + (size_t)b * CP * N2 + j0;

    int tid = threadIdx.x;
    if (tid < 128) {
        nAs[tid] = nAv[b * N1 + i0 + tid];
        nBs[tid] = nBv[b * N2 + j0 + tid];
    }

    int warp = tid >> 5, lane = tid & 31;
    int gid = lane >> 2, tig = lane & 3;
    int mi = warp * 16 + gid;

    float acc[16][4];
    #pragma unroll
    for (int nt = 0; nt < 16; nt++)
        #pragma unroll
        for (int u = 0; u < 4; u++) acc[nt][u] = 0.f;

    for (int kb = 0; kb < CP; kb += CPK) {
        for (int idx = tid; idx < CPK * 32 * 2; idx += 256) {
            int which = idx >= CPK * 32;
            int r = which ? idx - CPK * 32 : idx;
            int k = r >> 5, c4 = (r & 31) << 2;
            const float* src = which ? Bsrc : Asrc;
            float2* dst = (which ? Bs2 : As2) + k * S2 + c4;
            float4 v = *(const float4*)(src + (size_t)(kb + k) * 4096 + c4);
            float h;
            h = f2tf32f(v.x); dst[0] = make_float2(h, f2tf32f(v.x - h));
            h = f2tf32f(v.y); dst[1] = make_float2(h, f2tf32f(v.y - h));
            h = f2tf32f(v.z); dst[2] = make_float2(h, f2tf32f(v.z - h));
            h = f2tf32f(v.w); dst[3] = make_float2(h, f2tf32f(v.w - h));
        }
        __syncthreads();

        #pragma unroll
        for (int kk = 0; kk < CPK; kk += 8) {
            const float2* r0 = As2 + (kk + tig) * S2;
            const float2* r1 = As2 + (kk + tig + 4) * S2;
            float2 a0 = r0[mi], a1 = r0[mi + 8];
            float2 a2 = r1[mi], a3 = r1[mi + 8];
            const float2* q0 = Bs2 + (kk + tig) * S2;
            const float2* q1 = Bs2 + (kk + tig + 4) * S2;
            #pragma unroll
            for (int nt = 0; nt < 16; nt++) {
                int nb = nt * 8 + gid;
                float2 b0 = q0[nb], b1 = q1[nb];
                MMA_TF32(acc[nt], a0.y, a1.y, a2.y, a3.y, b0.x, b1.x);  // lo*hi
                MMA_TF32(acc[nt], a0.x, a1.x, a2.x, a3.x, b0.y, b1.y);  // hi*lo
                MMA_TF32(acc[nt], a0.x, a1.x, a2.x, a3.x, b0.x, b1.x);  // hi*hi
            }
        }
        __syncthreads();
    }

    float* drow = g_dist + (size_t)b * N1 * N2;
    float ni0 = nAs[mi], ni1 = nAs[mi + 8];
    size_t ro0 = (size_t)(i0 + mi) * N2 + j0;
    size_t ro1 = ro0 + (size_t)8 * N2;
    #pragma unroll
    for (int nt = 0; nt < 16; nt++) {
        int jc = nt * 8 + tig * 2;
        float nj0 = nBs[jc], nj1 = nBs[jc + 1];
        float2 o0, o1;
        o0.x = fmaxf(ni0 - 2.f * acc[nt][0] + nj0, 0.f);
        o0.y = fmaxf(ni0 - 2.f * acc[nt][1] + nj1, 0.f);
        o1.x = fmaxf(ni1 - 2.f * acc[nt][2] + nj0, 0.f);
        o1.y = fmaxf(ni1 - 2.f * acc[nt][3] + nj1, 0.f);
        *(float2*)(drow + ro0 + jc) = o0;
        *(float2*)(drow + ro1 + jc) = o1;
    }
}

// ---------------- top-K v3: float build + smem row cache + warp0 extraction ----------------
__global__ void __launch_bounds__(256) k_topk(int sel)
{
    __shared__ float vals[N2];                   // 16 KB row cache
    __shared__ unsigned long long segmin[256];   // 2 KB
    int q = blockIdx.x;
    const float* row = g_dist + (size_t)q * N2;
    int* idxo = sel ? g_idx2 : g_idx1;
    int tid = threadIdx.x;

    // build: float compares in ascending order (strict '<' keeps smallest index on ties)
    {
        int basej = tid * 16;
        float mv = __int_as_float(0x7f7fffff);   // FLT_MAX
        int mj = basej;
        #pragma unroll
        for (int i = 0; i < 4; i++) {
            float4 f = *(const float4*)(row + basej + i * 4);
            *(float4*)(vals + basej + i * 4) = f;
            int j0 = basej + i * 4;
            if (f.x < mv) { mv = f.x; mj = j0 + 0; }
            if (f.y < mv) { mv = f.y; mj = j0 + 1; }
            if (f.z < mv) { mv = f.z; mj = j0 + 2; }
            if (f.w < mv) { mv = f.w; mj = j0 + 3; }
        }
        segmin[tid] = ((unsigned long long)__float_as_uint(mv) << 32) | (unsigned)mj;
    }
    __syncthreads();

    // extraction in warp 0; seg s lives in r[s>>5] of lane (s&31)
    if (tid < 32) {
        int lane = tid;
        unsigned long long r[8];
        #pragma unroll
        for (int i = 0; i < 8; i++) r[i] = segmin[lane + 32 * i];
        int ex[KN];
        #pragma unroll
        for (int i = 0; i < KN; i++) ex[i] = -1;

        for (int k = 0; k < KN; k++) {
            unsigned long long m = r[0];
            #pragma unroll
            for (int i = 1; i < 8; i++) m = u64min(m, r[i]);
            #pragma unroll
            for (int o = 16; o; o >>= 1)
                m = u64min(m, __shfl_xor_sync(0xffffffffu, m, o));
            int j = (int)(unsigned)(m & 0xffffffffULL);
            #pragma unroll
            for (int i = 0; i < KN; i++) if (i == k) ex[i] = j;
            if (lane == 0) idxo[q * KN + k] = j;
            if (k == KN - 1) break;

            // rescan winning segment from smem cache, masking extracted indices
            int seg = j >> 4;
            unsigned long long v = ~0ull;
            if (lane < 16) {
                int idx = seg * 16 + lane;
                float f = vals[idx];
                v = ((unsigned long long)__float_as_uint(f) << 32) | (unsigned)idx;
                #pragma unroll
                for (int i = 0; i < KN; i++)
                    if (i <= k && ex[i] == idx) v = ~0ull;
            }
            #pragma unroll
            for (int o = 8; o; o >>= 1)
                v = u64min(v, __shfl_xor_sync(0xffffffffu, v, o));
            unsigned long long vb = __shfl_sync(0xffffffffu, v, 0);
            int slot = seg >> 5, ln = seg & 31;
            #pragma unroll
            for (int i = 0; i < 8; i++)
                if (i == slot && lane == ln) r[i] = vb;
        }
    }
}

// ---------------- fused MLP on tensor cores (bf16 3-term split, m16n8k16) ----------------
#define TNP 8
#define SY 132
#define MX   0
#define MYO  (144 * SY)
#define MWC  (MYO + 128 * SY)
#define MB   (MWC + 24 * SY * 2)
#define MH2  (MB + 384)
#define MSW2 (MH2 + 1024)
#define MSB2 (MSW2 + 1024)
#define MIDX (MSB2 + 128)
#define MLP2_SMEM ((MIDX + 128) * 4)

__global__ void __launch_bounds__(512) k_mlp_tc(
    const float* __restrict__ b0g, const float* __restrict__ b1g,
    const float* __restrict__ b2g,
    const float* __restrict__ n1w0, const float* __restrict__ n1b0,
    const float* __restrict__ n1w1, const float* __restrict__ n1b1,
    const float* __restrict__ n1w2, const float* __restrict__ n1b2)
{
    extern __shared__ float sm[];
    float* Xbuf = sm + MX;
    float* Ybuf = sm + MYO;
    uint2* Wc = (uint2*)(sm + MWC);
    float* biasS = sm + MB;
    float* h2s = sm + MH2;
    float* sw2 = sm + MSW2;
    float* sb2 = sm + MSB2;
    int* idxs = (int*)(sm + MIDX);

    int tid = threadIdx.x;
    int warp = tid >> 5, lane = tid & 31;
    int gid = lane >> 2, tig = lane & 3;
    int wm = warp & 7, nh = warp >> 3;
    int mi = wm * 16 + gid;
    int base = blockIdx.x * TNP;

    if (tid < 128) {
        idxs[tid] = g_idx1[base * KN + tid];
        #pragma unroll
        for (int r = 0; r < 8; r++) sw2[tid + 128 * r] = n1w2[tid + 128 * r];
        sb2[tid] = n1b2[tid];
        biasS[tid] = b0g[tid];
        biasS[128 + tid] = b1g[tid];
        biasS[256 + tid] = b2g[tid];
    }
    __syncthreads();

    for (int e = tid; e < 144 * 128; e += 512) {
        int i = e >> 7, col = e & 127;
        int tn = col >> 4;
        int pt = base + tn;
        int b = pt >> 12;
        int j = idxs[col];
        float v;
        if (i < 64) v = g_p1T[(size_t)pt * DD + i];
        else if (i < 128) v = g_p2T[((size_t)b * N2 + j) * DD + (i - 64)];
        else if (i < 131) v = g_x2T[(b * N2 + j) * 3 + (i - 128)] - g_x1T[pt * 3 + (i - 128)];
        else v = 0.f;
        Xbuf[i * SY + col] = v;
    }
    __syncthreads();

    if (tid < 128) {
        int col = tid;
        float dx0 = Xbuf[128 * SY + col];
        float dx1 = Xbuf[129 * SY + col];
        float dx2 = Xbuf[130 * SY + col];
        float h[8];
        #pragma unroll
        for (int j = 0; j < 8; j++) {
            float s = n1w0[j * 3 + 0] * dx0 + n1w0[j * 3 + 1] * dx1 + n1w0[j * 3 + 2] * dx2 + n1b0[j];
            h[j] = fmaxf(s, 0.f);
        }
        #pragma unroll
        for (int j = 0; j < 8; j++) {
            float s = n1b1[j];
            #pragma unroll
            for (int m = 0; m < 8; m++) s += n1w1[j * 8 + m] * h[m];
            h2s[col * 8 + j] = fmaxf(s, 0.f);
        }
    }

    #pragma unroll 1
    for (int l = 0; l < 3; l++) {
        const int KPL = (l == 0) ? 72 : 64;
        const float* Xin = (l == 1) ? Ybuf : Xbuf;
        float* Yout = (l == 1) ? Xbuf : Ybuf;

        float acc[8][4];
        #pragma unroll
        for (int nti = 0; nti < 8; nti++) {
            int c0 = (nh * 8 + nti) * 8 + tig * 2;
            acc[nti][0] = biasS[l * 128 + c0];
            acc[nti][1] = biasS[l * 128 + c0 + 1];
            acc[nti][2] = acc[nti][0];
            acc[nti][3] = acc[nti][1];
        }

        for (int kbp = 0; kbp < KPL; kbp += 24) {
            int cs = (KPL - kbp < 24) ? (KPL - kbp) : 24;
            __syncthreads();
            for (int e = tid; e < cs * 128; e += 512) {
                int kl = e >> 7, c = e & 127;
                Wc[kl * SY + c] = g_wbf[l][kbp + kl][c];
            }
            __syncthreads();
            for (int pp = 0; pp < cs; pp += 8) {
                int kp0 = kbp + pp + tig;
                int kp1 = kp0 + 4;
                int r00 = 2 * kp0, r10 = 2 * kp1;
                float x00 = Xin[r00 * SY + mi];
                float x01 = Xin[(r00 + 1) * SY + mi];
                float x02 = Xin[r00 * SY + mi + 8];
                float x03 = Xin[(r00 + 1) * SY + mi + 8];
                float x10 = Xin[r10 * SY + mi];
                float x11 = Xin[(r10 + 1) * SY + mi];
                float x12 = Xin[r10 * SY + mi + 8];
                float x13 = Xin[(r10 + 1) * SY + mi + 8];
                float h00 = bf16_trunc(x00), h01 = bf16_trunc(x01);
                float h02 = bf16_trunc(x02), h03 = bf16_trunc(x03);
                float h10 = bf16_trunc(x10), h11 = bf16_trunc(x11);
                float h12 = bf16_trunc(x12), h13 = bf16_trunc(x13);
                unsigned a0h = packbf2(h00, h01), a1h = packbf2(h02, h03);
                unsigned a2h = packbf2(h10, h11), a3h = packbf2(h12, h13);
                unsigned a0l = packbf2(x00 - h00, x01 - h01);
                unsigned a1l = packbf2(x02 - h02, x03 - h03);
                unsigned a2l = packbf2(x10 - h10, x11 - h11);
                unsigned a3l = packbf2(x12 - h12, x13 - h13);
                const uint2* w0p = Wc + (pp + tig) * SY;
                const uint2* w1p = Wc + (pp + tig + 4) * SY;
                #pragma unroll
                for (int nti = 0; nti < 8; nti++) {
                    int nb = (nh * 8 + nti) * 8 + gid;
                    uint2 b0 = w0p[nb], b1 = w1p[nb];
                    MMA_BF16(acc[nti], a0l, a1l, a2l, a3l, b0.x, b1.x);
                    MMA_BF16(acc[nti], a0h, a1h, a2h, a3h, b0.y, b1.y);
                    MMA_BF16(acc[nti], a0h, a1h, a2h, a3h, b0.x, b1.x);
                }
            }
        }
        __syncthreads();
        #pragma unroll
        for (int nti = 0; nti < 8; nti++) {
            int c0 = (nh * 8 + nti) * 8 + tig * 2;
            Yout[c0 * SY + mi] = leakyf(acc[nti][0]);
            Yout[(c0 + 1) * SY + mi] = leakyf(acc[nti][1]);
            Yout[c0 * SY + mi + 8] = leakyf(acc[nti][2]);
            Yout[(c0 + 1) * SY + mi + 8] = leakyf(acc[nti][3]);
        }
    }
    __syncthreads();

    {
        int col = tid >> 2, cq = tid & 3;
        float hj[8];
        #pragma unroll
        for (int j = 0; j < 8; j++) hj[j] = h2s[col * 8 + j];
        #pragma unroll 4
        for (int cc = 0; cc < 32; cc++) {
            int c = cq * 32 + cc;
            float s = sb2[c];
            #pragma unroll
            for (int j = 0; j < 8; j++) s += sw2[c * 8 + j] * hj[j];
            Xbuf[col * SY + c] = fmaxf(s, 0.f);
        }
    }
    __syncthreads();

    for (int e = tid; e < 1024; e += 512) {
        int pt = e >> 7, c = e & 127;
        const float* yr = Ybuf + c * SY + pt * 16;
        const float* sc = Xbuf + (pt * 16) * SY + c;
        float a = 0.f;
        #pragma unroll
        for (int k = 0; k < 16; k++) a += sc[k * SY] * yr[k];
        g_p2p[(size_t)(base + pt) * CO + c] = a;
    }
}

// ---------------- patch aggregation ----------------
__global__ void __launch_bounds__(128) k_patch(
    const float* __restrict__ n2w0, const float* __restrict__ n2b0,
    const float* __restrict__ n2w1, const float* __restrict__ n2b1,
    const float* __restrict__ n2w2, const float* __restrict__ n2b2,
    float* __restrict__ out)
{
    __shared__ float h2s[16][8];
    __shared__ int js[16];
    int q = blockIdx.x;
    int b = q / N1, n = q % N1;
    int tid = threadIdx.x;
    if (tid < 16) {
        int j = g_idx2[q * KN + tid];
        js[tid] = j;
        float dx0 = g_x1T[(b * N1 + j) * 3 + 0] - g_x1T[q * 3 + 0];
        float dx1 = g_x1T[(b * N1 + j) * 3 + 1] - g_x1T[q * 3 + 1];
        float dx2 = g_x1T[(b * N1 + j) * 3 + 2] - g_x1T[q * 3 + 2];
        float h[8];
        #pragma unroll
        for (int jj = 0; jj < 8; jj++) {
            float s = n2w0[jj * 3 + 0] * dx0 + n2w0[jj * 3 + 1] * dx1 + n2w0[jj * 3 + 2] * dx2 + n2b0[jj];
            h[jj] = fmaxf(s, 0.f);
        }
        #pragma unroll
        for (int jj = 0; jj < 8; jj++) {
            float s = n2b1[jj];
            #pragma unroll
            for (int m = 0; m < 8; m++) s += n2w1[jj * 8 + m] * h[m];
            h2s[tid][jj] = fmaxf(s, 0.f);
        }
    }
    __syncthreads();
    int c = tid;
    float w2r[8];
    #pragma unroll
    for (int j = 0; j < 8; j++) w2r[j] = n2w2[c * 8 + j];
    float bc = n2b2[c];
    float acc = 0.f;
    #pragma unroll
    for (int k = 0; k < KN; k++) {
        float s = bc;
        #pragma unroll
        for (int j = 0; j < 8; j++) s += w2r[j] * h2s[k][j];
        s = fmaxf(s, 0.f);
        acc += s * g_p2p[((size_t)b * N1 + js[k]) * CO + c];
    }
    out[(size_t)b * CO * N1 + (size_t)c * N1 + n] = acc;
}

// ---------------- launch ----------------
extern "C" void kernel_launch(void* const* d_in, const int* in_sizes, int n_in,
                              void* d_out, int out_size)
{
    int s = (n_in >= 31) ? 0 : -2;
    const float* xyz1 = (const float*)d_in[0];
    const float* xyz2 = (const float*)d_in[1];
    const float* pts1 = (const float*)d_in[2];
    const float* pts2 = (const float*)d_in[3];
    const float* vel1 = (const float*)d_in[4];
    const float* fcc  = (const float*)d_in[8 + s];
    const float* fcv  = (const float*)d_in[9 + s];
    const float* wxyz = (const float*)d_in[10 + s];
    const float* wpts = (const float*)d_in[12 + s];
    const float* mw0 = (const float*)d_in[13 + s];
    const float* mb0 = (const float*)d_in[14 + s];
    const float* mw1 = (const float*)d_in[15 + s];
    const float* mb1 = (const float*)d_in[16 + s];
    const float* mw2 = (const float*)d_in[17 + s];
    const float* mb2 = (const float*)d_in[18 + s];
    const float* n1w0 = (const float*)d_in[19 + s];
    const float* n1b0 = (const float*)d_in[20 + s];
    const float* n2w0 = (const float*)d_in[21 + s];
    const float* n2b0 = (const float*)d_in[22 + s];
    const float* n1w1 = (const float*)d_in[23 + s];
    const float* n1b1 = (const float*)d_in[24 + s];
    const float* n2w1 = (const float*)d_in[25 + s];
    const float* n2b1 = (const float*)d_in[26 + s];
    const float* n1w2 = (const float*)d_in[27 + s];
    const float* n1b2 = (const float*)d_in[28 + s];
    const float* n2w2 = (const float*)d_in[29 + s];
    const float* n2b2 = (const float*)d_in[30 + s];

    float* out = (float*)d_out;
    const int patch_elems = BATCH * CO * N1;
    const int vw_elems = BATCH * N1 * 3;
    float* out_vw = (out_size >= patch_elems + vw_elems) ? (out + patch_elems) : nullptr;

    cudaFuncSetAttribute(k_mlp_tc, cudaFuncAttributeMaxDynamicSharedMemorySize, (int)MLP2_SMEM);
    cudaFuncSetAttribute(k_dist_tc, cudaFuncAttributeMaxDynamicSharedMemorySize, (int)DIST_SMEM);

    const int prep_total = 2 * BATCH * CP * N1 + 2 * BATCH * 3 * N1;
    dim3 gg(N2 / 128, N1 / 128, BATCH);
    dim3 gt(N1 / 32, 2 * BATCH * 2);

    // order: topk0 is the 4th launch -> ncu lands on the new top-k
    k_prep<<<(prep_total + 255) / 256, 256>>>(xyz1, xyz2, pts1, pts2, wxyz, wpts);
    k_normsAB<<<(BATCH * 4096 + 127) / 128, 128>>>();
    k_dist_tc<<<gg, 256, DIST_SMEM>>>(0);
    k_topk<<<BATCH * N1, 256>>>(0);
    k_rigid<<<(BATCH * N1 + 127) / 128, 128>>>(xyz1, vel1, fcc, fcv, out_vw);
    k_nc<<<(BATCH * N1 + 127) / 128, 128>>>();
    k_transp<<<gt, 256>>>(pts1, pts2);
    k_wprep<<<108, 256>>>(mw0, mw1, mw2);
    k_mlp_tc<<<(BATCH * N1) / TNP, 512, MLP2_SMEM>>>(mb0, mb1, mb2,
                                                     n1w0, n1b0, n1w1, n1b1, n1w2, n1b2);
    k_comb<<<(BATCH * CP * N1 + 255) / 256, 256>>>();
    k_dist_tc<<<gg, 256, DIST_SMEM>>>(1);
    k_topk<<<BATCH * N1, 256>>>(1);
    k_patch<<<BATCH * N1, 128>>>(n2w0, n2b0, n2w1, n2b1, n2w2, n2b2, out);
}

// round 12
// speedup vs baseline: 1.0618x; 1.0618x over previous
#include <cuda_runtime.h>
#include <cuda_bf16.h>
#include <math.h>

#define BATCH 2
#define N1 4096
#define N2 4096
#define DD 64
#define KN 16
#define KCC 8
#define CP 80      // padded feature channels (67 / 70 used)
#define CO 128

// ---------------- scratch (static device memory; no runtime alloc) ----------------
__device__ float g_dist[(size_t)BATCH * N1 * N2];        // 134 MB
__device__ float g_F1[BATCH * CP * N1];
__device__ float g_F2[BATCH * CP * N2];
__device__ float g_CB[BATCH * CP * N1];
__device__ float g_nA[BATCH * N1];
__device__ float g_nB[BATCH * N2];
__device__ float g_nC[BATCH * N1];
__device__ int   g_idx1[BATCH * N1 * KN];
__device__ int   g_idx2[BATCH * N1 * KN];
__device__ float g_vw[BATCH * N1 * 3];
__device__ float g_wf[BATCH * N1];
__device__ float g_wr[BATCH * N1];
__device__ float g_p1T[BATCH * N1 * DD];
__device__ float g_p2T[BATCH * N2 * DD];
__device__ float g_x1T[BATCH * N1 * 3];
__device__ float g_x2T[BATCH * N2 * 3];
__device__ float g_p2p[(size_t)BATCH * N1 * CO];
__device__ uint2 g_wbf[3][72][128];     // bf16 hi/lo split, transposed MLP weights (k-pairs)

__device__ __forceinline__ float leakyf(float x) { return x >= 0.f ? x : 0.1f * x; }
__device__ __forceinline__ unsigned long long u64min(unsigned long long a, unsigned long long b) {
    return a < b ? a : b;
}

// ---- tf32 helpers (dist kernel) ----
__device__ __forceinline__ float f2tf32f(float x) {
    unsigned int r;
    asm("cvt.rna.tf32.f32 %0, %1;" : "=r"(r) : "f"(x));
    return __uint_as_float(r);
}

#define MMA_TF32(acc, A0, A1, A2, A3, B0, B1)                                   \
    asm volatile("mma.sync.aligned.m16n8k8.row.col.f32.tf32.tf32.f32 "          \
                 "{%0,%1,%2,%3}, {%4,%5,%6,%7}, {%8,%9}, {%0,%1,%2,%3};"        \
                 : "+f"(acc[0]), "+f"(acc[1]), "+f"(acc[2]), "+f"(acc[3])       \
                 : "r"(__float_as_uint(A0)), "r"(__float_as_uint(A1)),          \
                   "r"(__float_as_uint(A2)), "r"(__float_as_uint(A3)),          \
                   "r"(__float_as_uint(B0)), "r"(__float_as_uint(B1)))

// ---- bf16 helpers (mlp kernel) ----
__device__ __forceinline__ float bf16_trunc(float x) {          // exact split: top 16 bits
    return __uint_as_float(__float_as_uint(x) & 0xffff0000u);
}
__device__ __forceinline__ unsigned packbf2(float lo_elem, float hi_elem) {
    __nv_bfloat162 v = __floats2bfloat162_rn(lo_elem, hi_elem); // .x = first arg (low half)
    return *(unsigned*)&v;
}

#define MMA_BF16(acc, A0, A1, A2, A3, B0, B1)                                   \
    asm volatile("mma.sync.aligned.m16n8k16.row.col.f32.bf16.bf16.f32 "         \
                 "{%0,%1,%2,%3}, {%4,%5,%6,%7}, {%8,%9}, {%0,%1,%2,%3};"        \
                 : "+f"(acc[0]), "+f"(acc[1]), "+f"(acc[2]), "+f"(acc[3])       \
                 : "r"(A0), "r"(A1), "r"(A2), "r"(A3), "r"(B0), "r"(B1))

// ---------------- rigid 3x3 least squares + mask ----------------
__global__ void k_rigid(const float* __restrict__ xyz1, const float* __restrict__ vel1,
                        const float* __restrict__ fcc, const float* __restrict__ fcv,
                        float* __restrict__ out_vw)
{
    int t = blockIdx.x * blockDim.x + threadIdx.x;
    if (t >= BATCH * N1) return;
    int b = t / N1, n = t % N1;
    const float* cc = fcc + (size_t)t * KCC * 3;
    const float* cv = fcv + (size_t)t * KCC;
    double A00 = 1e-6, A01 = 0, A02 = 0, A11 = 1e-6, A12 = 0, A22 = 1e-6;
    double r0 = 0, r1 = 0, r2 = 0;
    for (int k = 0; k < KCC; k++) {
        double x = cc[k * 3 + 0], y = cc[k * 3 + 1], z = cc[k * 3 + 2];
        double inv = 1.0 / sqrt(x * x + y * y + z * z);
        x *= inv; y *= inv; z *= inv;
        A00 += x * x; A01 += x * y; A02 += x * z;
        A11 += y * y; A12 += y * z; A22 += z * z;
        double v = (double)cv[k];
        r0 += x * v; r1 += y * v; r2 += z * v;
    }
    double c00 = A11 * A22 - A12 * A12;
    double c01 = A01 * A22 - A12 * A02;
    double c02 = A01 * A12 - A11 * A02;
    double det = A00 * c00 - A01 * c01 + A02 * c02;
    double id = 1.0 / det;
    double v0 = (r0 * c00 - A01 * (r1 * A22 - A12 * r2) + A02 * (r1 * A12 - A11 * r2)) * id;
    double v1 = (A00 * (r1 * A22 - A12 * r2) - r0 * c01 + A02 * (A01 * r2 - r1 * A02)) * id;
    double v2 = (A00 * (A11 * r2 - r1 * A12) - A01 * (A01 * r2 - r1 * A02) + r0 * c02) * id;

    float fx = xyz1[(b * 3 + 0) * N1 + n];
    float fy = xyz1[(b * 3 + 1) * N1 + n];
    float fz = xyz1[(b * 3 + 2) * N1 + n];
    double inl = 1.0 / sqrt((double)fx * fx + (double)fy * fy + (double)fz * fz);
    double err = fabs((v0 * fx + v1 * fy + v2 * fz) * inl - (double)vel1[t]);
    bool m = (err <= 5.0);
    g_wf[t] = m ? 0.1f : 0.9f;
    g_wr[t] = m ? 0.9f : 0.1f;
    g_vw[t * 3 + 0] = (float)v0;
    g_vw[t * 3 + 1] = (float)v1;
    g_vw[t * 3 + 2] = (float)v2;
    if (out_vw) {
        out_vw[t * 3 + 0] = (float)v0;
        out_vw[t * 3 + 1] = (float)v1;
        out_vw[t * 3 + 2] = (float)v2;
    }
}

// ---------------- fused: weighted feature build + xyz transposes ----------------
__global__ void k_prep(const float* __restrict__ xyz1, const float* __restrict__ xyz2,
                       const float* __restrict__ pts1, const float* __restrict__ pts2,
                       const float* __restrict__ wxyz_p, const float* __restrict__ wpts_p)
{
    float wx = *wxyz_p, wp = *wpts_p;
    const int totalF = BATCH * CP * N1;
    const int tx3 = BATCH * 3 * N1;
    const int total = 2 * totalF + 2 * tx3;
    for (int e = blockIdx.x * blockDim.x + threadIdx.x; e < total;
         e += gridDim.x * blockDim.x) {
        if (e < 2 * totalF) {
            int which = e / totalF;
            int r = e % totalF;
            int b = r / (CP * N1);
            int c = (r / N1) % CP;
            int n = r % N1;
            const float* xyz = which ? xyz2 : xyz1;
            const float* pts = which ? pts2 : pts1;
            float* F = which ? g_F2 : g_F1;
            float v = 0.f;
            if (c < 3) v = wx * xyz[(b * 3 + c) * N1 + n];
            else if (c < 67) v = wp * pts[(b * DD + (c - 3)) * N1 + n];
            F[r] = v;
        } else {
            int r = e - 2 * totalF;
            if (r < tx3) {
                int b = r / (3 * N1), c = (r / N1) % 3, n = r % N1;
                g_x1T[(b * N1 + n) * 3 + c] = xyz1[r];
            } else {
                r -= tx3;
                int b = r / (3 * N1), c = (r / N1) % 3, n = r % N1;
                g_x2T[(b * N2 + n) * 3 + c] = xyz2[r];
            }
        }
    }
}

// ---------------- MLP weight transpose + bf16 hi/lo split (runs once) ----------------
__global__ void k_wprep(const float* __restrict__ w0, const float* __restrict__ w1,
                        const float* __restrict__ w2)
{
    const int per = 72 * 128;
    for (int e = blockIdx.x * blockDim.x + threadIdx.x; e < 3 * per;
         e += gridDim.x * blockDim.x) {
        int l = e / per;
        int r = e % per;
        int kp = r >> 7, c = r & 127;
        int KD = (l == 0) ? 131 : 128;
        const float* w = (l == 0) ? w0 : (l == 1) ? w1 : w2;
        int k0 = 2 * kp, k1 = 2 * kp + 1;
        float v0 = (k0 < KD) ? w[c * KD + k0] : 0.f;
        float v1 = (k1 < KD) ? w[c * KD + k1] : 0.f;
        float h0 = bf16_trunc(v0), h1 = bf16_trunc(v1);
        uint2 o;
        o.x = packbf2(h0, h1);
        o.y = packbf2(v0 - h0, v1 - h1);
        g_wbf[l][kp][c] = o;
    }
}

// ---------------- coalesced tiled transpose: [B][C][N] -> [B][N][C], C=64 ----------------
__global__ void __launch_bounds__(256) k_transp(const float* __restrict__ src1,
                                                const float* __restrict__ src2)
{
    __shared__ float t[32][33];
    int zc = blockIdx.y;
    int ct = zc & 1;
    int b = (zc >> 1) & (BATCH - 1);
    int which = zc >> 2;
    const float* src = which ? src2 : src1;
    float* dst = which ? g_p2T : g_p1T;
    int n0 = blockIdx.x * 32;
    int c0 = ct * 32;
    int lx = threadIdx.x & 31, ly = threadIdx.x >> 5;
    #pragma unroll
    for (int r = 0; r < 4; r++) {
        int c = c0 + ly + r * 8;
        t[ly + r * 8][lx] = src[((size_t)b * DD + c) * N1 + n0 + lx];
    }
    __syncthreads();
    #pragma unroll
    for (int r = 0; r < 4; r++) {
        int n = n0 + ly + r * 8;
        dst[((size_t)b * N1 + n) * DD + c0 + lx] = t[lx][ly + r * 8];
    }
}

// ---------------- squared norms of F1/F2 (no rigid dependency) ----------------
__global__ void k_normsAB()
{
    int t = blockIdx.x * blockDim.x + threadIdx.x;
    if (t >= BATCH * 4096) return;
    int b = t / 4096, n = t % 4096;
    float sA = 0.f, sB = 0.f;
    #pragma unroll 8
    for (int c = 0; c < CP; c++) {
        float a = g_F1[(b * CP + c) * 4096 + n];
        float bb = g_F2[(b * CP + c) * 4096 + n];
        sA += a * a;
        sB += bb * bb;
    }
    g_nA[t] = sA;
    g_nB[t] = sB;
}

// ---------------- comb norm (needs rigid + normsAB) ----------------
__global__ void k_nc()
{
    int t = blockIdx.x * blockDim.x + threadIdx.x;
    if (t >= BATCH * N1) return;
    float wf = g_wf[t], wr = g_wr[t];
    float v0 = g_vw[t * 3 + 0], v1 = g_vw[t * 3 + 1], v2 = g_vw[t * 3 + 2];
    g_nC[t] = wf * wf * g_nA[t] + wr * wr * (v0 * v0 + v1 * v1 + v2 * v2);
}

// ---------------- comb features for second KNN ----------------
__global__ void k_comb()
{
    const int total = BATCH * CP * N1;
    for (int e = blockIdx.x * blockDim.x + threadIdx.x; e < total;
         e += gridDim.x * blockDim.x) {
        int b = e / (CP * N1);
        int c = (e / N1) % CP;
        int n = e % N1;
        float v = 0.f;
        if (c < 67) v = g_wf[b * N1 + n] * g_F1[e];
        else if (c < 70) v = g_wr[b * N1 + n] * g_vw[(b * N1 + n) * 3 + (c - 67)];
        g_CB[e] = v;
    }
}

// ---------------- distance GEMM on tensor cores (3xTF32, hi/lo interleaved) ----------------
#define CPK 16
#define S2 132
#define SLAB2 (CPK * S2)
#define DIST_SMEM ((2 * SLAB2 * 2 + 256) * 4)

__global__ void __launch_bounds__(256) k_dist_tc(int sel)
{
    extern __shared__ float2 dsm2[];
    float2* As2 = dsm2;                 // [CPK][S2] (hi,lo)
    float2* Bs2 = As2 + SLAB2;
    float* nAs = (float*)(Bs2 + SLAB2); // 128
    float* nBs = nAs + 128;             // 128

    const float* FA = sel ? g_CB : g_F1;
    const float* FB = sel ? g_CB : g_F2;
    const float* nAv = sel ? g_nC : g_nA;
    const float* nBv = sel ? g_nC : g_nB;

    int b = blockIdx.z;
    int i0 = blockIdx.y * 128, j0 = blockIdx.x * 128;
    const float* Asrc = FA + (size_t)b * CP * N1 + i0;
    const float* Bsrc = FB + (size_t)b * CP * N2 + j0;

    int tid = threadIdx.x;
    if (tid < 128) {
        nAs[tid] = nAv[b * N1 + i0 + tid];
        nBs[tid] = nBv[b * N2 + j0 + tid];
    }

    int warp = tid >> 5, lane = tid & 31;
    int gid = lane >> 2, tig = lane & 3;
    int mi = warp * 16 + gid;

    float acc[16][4];
    #pragma unroll
    for (int nt = 0; nt < 16; nt++)
        #pragma unroll
        for (int u = 0; u < 4; u++) acc[nt][u] = 0.f;

    for (int kb = 0; kb < CP; kb += CPK) {
        for (int idx = tid; idx < CPK * 32 * 2; idx += 256) {
            int which = idx >= CPK * 32;
            int r = which ? idx - CPK * 32 : idx;
            int k = r >> 5, c4 = (r & 31) << 2;
            const float* src = which ? Bsrc : Asrc;
            float2* dst = (which ? Bs2 : As2) + k * S2 + c4;
            float4 v = *(const float4*)(src + (size_t)(kb + k) * 4096 + c4);
            float h;
            h = f2tf32f(v.x); dst[0] = make_float2(h, f2tf32f(v.x - h));
            h = f2tf32f(v.y); dst[1] = make_float2(h, f2tf32f(v.y - h));
            h = f2tf32f(v.z); dst[2] = make_float2(h, f2tf32f(v.z - h));
            h = f2tf32f(v.w); dst[3] = make_float2(h, f2tf32f(v.w - h));
        }
        __syncthreads();

        #pragma unroll
        for (int kk = 0; kk < CPK; kk += 8) {
            const float2* r0 = As2 + (kk + tig) * S2;
            const float2* r1 = As2 + (kk + tig + 4) * S2;
            float2 a0 = r0[mi], a1 = r0[mi + 8];
            float2 a2 = r1[mi], a3 = r1[mi + 8];
            const float2* q0 = Bs2 + (kk + tig) * S2;
            const float2* q1 = Bs2 + (kk + tig + 4) * S2;
            #pragma unroll
            for (int nt = 0; nt < 16; nt++) {
                int nb = nt * 8 + gid;
                float2 b0 = q0[nb], b1 = q1[nb];
                MMA_TF32(acc[nt], a0.y, a1.y, a2.y, a3.y, b0.x, b1.x);  // lo*hi
                MMA_TF32(acc[nt], a0.x, a1.x, a2.x, a3.x, b0.y, b1.y);  // hi*lo
                MMA_TF32(acc[nt], a0.x, a1.x, a2.x, a3.x, b0.x, b1.x);  // hi*hi
            }
        }
        __syncthreads();
    }

    float* drow = g_dist + (size_t)b * N1 * N2;
    float ni0 = nAs[mi], ni1 = nAs[mi + 8];
    size_t ro0 = (size_t)(i0 + mi) * N2 + j0;
    size_t ro1 = ro0 + (size_t)8 * N2;
    #pragma unroll
    for (int nt = 0; nt < 16; nt++) {
        int jc = nt * 8 + tig * 2;
        float nj0 = nBs[jc], nj1 = nBs[jc + 1];
        float2 o0, o1;
        o0.x = fmaxf(ni0 - 2.f * acc[nt][0] + nj0, 0.f);
        o0.y = fmaxf(ni0 - 2.f * acc[nt][1] + nj1, 0.f);
        o1.x = fmaxf(ni1 - 2.f * acc[nt][2] + nj0, 0.f);
        o1.y = fmaxf(ni1 - 2.f * acc[nt][3] + nj1, 0.f);
        *(float2*)(drow + ro0 + jc) = o0;
        *(float2*)(drow + ro1 + jc) = o1;
    }
}

// ---------------- top-K v4: float build (low ALU) + 2KB smem + gmem rescan extraction ----------------
__global__ void __launch_bounds__(256) k_topk(int sel)
{
    __shared__ unsigned long long segmin[256];   // 2 KB total smem
    int q = blockIdx.x;
    const float* row = g_dist + (size_t)q * N2;
    int* idxo = sel ? g_idx2 : g_idx1;
    int tid = threadIdx.x;

    // build: float compares in ascending order (strict '<' keeps smallest index on ties)
    {
        int basej = tid * 16;
        float mv = __int_as_float(0x7f7fffff);   // FLT_MAX
        int mj = basej;
        #pragma unroll
        for (int i = 0; i < 4; i++) {
            float4 f = *(const float4*)(row + basej + i * 4);
            int j0 = basej + i * 4;
            if (f.x < mv) { mv = f.x; mj = j0 + 0; }
            if (f.y < mv) { mv = f.y; mj = j0 + 1; }
            if (f.z < mv) { mv = f.z; mj = j0 + 2; }
            if (f.w < mv) { mv = f.w; mj = j0 + 3; }
        }
        segmin[tid] = ((unsigned long long)__float_as_uint(mv) << 32) | (unsigned)mj;
    }
    __syncthreads();

    // extraction in warp 0; seg s lives in r[s>>5] of lane (s&31)
    if (tid < 32) {
        int lane = tid;
        unsigned long long r[8];
        #pragma unroll
        for (int i = 0; i < 8; i++) r[i] = segmin[lane + 32 * i];
        int ex[KN];
        #pragma unroll
        for (int i = 0; i < KN; i++) ex[i] = -1;

        for (int k = 0; k < KN; k++) {
            unsigned long long m = r[0];
            #pragma unroll
            for (int i = 1; i < 8; i++) m = u64min(m, r[i]);
            #pragma unroll
            for (int o = 16; o; o >>= 1)
                m = u64min(m, __shfl_xor_sync(0xffffffffu, m, o));
            int j = (int)(unsigned)(m & 0xffffffffULL);
            #pragma unroll
            for (int i = 0; i < KN; i++) if (i == k) ex[i] = j;
            if (lane == 0) idxo[q * KN + k] = j;
            if (k == KN - 1) break;

            // rescan winning segment from gmem (L2-hot), masking extracted indices
            int seg = j >> 4;
            unsigned long long v = ~0ull;
            if (lane < 16) {
                int idx = seg * 16 + lane;
                float f = __ldg(row + idx);
                v = ((unsigned long long)__float_as_uint(f) << 32) | (unsigned)idx;
                #pragma unroll
                for (int i = 0; i < KN; i++)
                    if (i <= k && ex[i] == idx) v = ~0ull;
            }
            #pragma unroll
            for (int o = 8; o; o >>= 1)
                v = u64min(v, __shfl_xor_sync(0xffffffffu, v, o));
            unsigned long long vb = __shfl_sync(0xffffffffu, v, 0);
            int slot = seg >> 5, ln = seg & 31;
            #pragma unroll
            for (int i = 0; i < 8; i++)
                if (i == slot && lane == ln) r[i] = vb;
        }
    }
}

// ---------------- fused MLP on tensor cores (bf16 3-term split, m16n8k16) ----------------
#define TNP 8
#define SY 132
#define MX   0
#define MYO  (144 * SY)
#define MWC  (MYO + 128 * SY)
#define MB   (MWC + 24 * SY * 2)
#define MH2  (MB + 384)
#define MSW2 (MH2 + 1024)
#define MSB2 (MSW2 + 1024)
#define MIDX (MSB2 + 128)
#define MLP2_SMEM ((MIDX + 128) * 4)

__global__ void __launch_bounds__(512) k_mlp_tc(
    const float* __restrict__ b0g, const float* __restrict__ b1g,
    const float* __restrict__ b2g,
    const float* __restrict__ n1w0, const float* __restrict__ n1b0,
    const float* __restrict__ n1w1, const float* __restrict__ n1b1,
    const float* __restrict__ n1w2, const float* __restrict__ n1b2)
{
    extern __shared__ float sm[];
    float* Xbuf = sm + MX;
    float* Ybuf = sm + MYO;
    uint2* Wc = (uint2*)(sm + MWC);
    float* biasS = sm + MB;
    float* h2s = sm + MH2;
    float* sw2 = sm + MSW2;
    float* sb2 = sm + MSB2;
    int* idxs = (int*)(sm + MIDX);

    int tid = threadIdx.x;
    int warp = tid >> 5, lane = tid & 31;
    int gid = lane >> 2, tig = lane & 3;
    int wm = warp & 7, nh = warp >> 3;
    int mi = wm * 16 + gid;
    int base = blockIdx.x * TNP;

    if (tid < 128) {
        idxs[tid] = g_idx1[base * KN + tid];
        #pragma unroll
        for (int r = 0; r < 8; r++) sw2[tid + 128 * r] = n1w2[tid + 128 * r];
        sb2[tid] = n1b2[tid];
        biasS[tid] = b0g[tid];
        biasS[128 + tid] = b1g[tid];
        biasS[256 + tid] = b2g[tid];
    }
    __syncthreads();

    for (int e = tid; e < 144 * 128; e += 512) {
        int i = e >> 7, col = e & 127;
        int tn = col >> 4;
        int pt = base + tn;
        int b = pt >> 12;
        int j = idxs[col];
        float v;
        if (i < 64) v = g_p1T[(size_t)pt * DD + i];
        else if (i < 128) v = g_p2T[((size_t)b * N2 + j) * DD + (i - 64)];
        else if (i < 131) v = g_x2T[(b * N2 + j) * 3 + (i - 128)] - g_x1T[pt * 3 + (i - 128)];
        else v = 0.f;
        Xbuf[i * SY + col] = v;
    }
    __syncthreads();

    if (tid < 128) {
        int col = tid;
        float dx0 = Xbuf[128 * SY + col];
        float dx1 = Xbuf[129 * SY + col];
        float dx2 = Xbuf[130 * SY + col];
        float h[8];
        #pragma unroll
        for (int j = 0; j < 8; j++) {
            float s = n1w0[j * 3 + 0] * dx0 + n1w0[j * 3 + 1] * dx1 + n1w0[j * 3 + 2] * dx2 + n1b0[j];
            h[j] = fmaxf(s, 0.f);
        }
        #pragma unroll
        for (int j = 0; j < 8; j++) {
            float s = n1b1[j];
            #pragma unroll
            for (int m = 0; m < 8; m++) s += n1w1[j * 8 + m] * h[m];
            h2s[col * 8 + j] = fmaxf(s, 0.f);
        }
    }

    #pragma unroll 1
    for (int l = 0; l < 3; l++) {
        const int KPL = (l == 0) ? 72 : 64;
        const float* Xin = (l == 1) ? Ybuf : Xbuf;
        float* Yout = (l == 1) ? Xbuf : Ybuf;

        float acc[8][4];
        #pragma unroll
        for (int nti = 0; nti < 8; nti++) {
            int c0 = (nh * 8 + nti) * 8 + tig * 2;
            acc[nti][0] = biasS[l * 128 + c0];
            acc[nti][1] = biasS[l * 128 + c0 + 1];
            acc[nti][2] = acc[nti][0];
            acc[nti][3] = acc[nti][1];
        }

        for (int kbp = 0; kbp < KPL; kbp += 24) {
            int cs = (KPL - kbp < 24) ? (KPL - kbp) : 24;
            __syncthreads();
            for (int e = tid; e < cs * 128; e += 512) {
                int kl = e >> 7, c = e & 127;
                Wc[kl * SY + c] = g_wbf[l][kbp + kl][c];
            }
            __syncthreads();
            for (int pp = 0; pp < cs; pp += 8) {
                int kp0 = kbp + pp + tig;
                int kp1 = kp0 + 4;
                int r00 = 2 * kp0, r10 = 2 * kp1;
                float x00 = Xin[r00 * SY + mi];
                float x01 = Xin[(r00 + 1) * SY + mi];
                float x02 = Xin[r00 * SY + mi + 8];
                float x03 = Xin[(r00 + 1) * SY + mi + 8];
                float x10 = Xin[r10 * SY + mi];
                float x11 = Xin[(r10 + 1) * SY + mi];
                float x12 = Xin[r10 * SY + mi + 8];
                float x13 = Xin[(r10 + 1) * SY + mi + 8];
                float h00 = bf16_trunc(x00), h01 = bf16_trunc(x01);
                float h02 = bf16_trunc(x02), h03 = bf16_trunc(x03);
                float h10 = bf16_trunc(x10), h11 = bf16_trunc(x11);
                float h12 = bf16_trunc(x12), h13 = bf16_trunc(x13);
                unsigned a0h = packbf2(h00, h01), a1h = packbf2(h02, h03);
                unsigned a2h = packbf2(h10, h11), a3h = packbf2(h12, h13);
                unsigned a0l = packbf2(x00 - h00, x01 - h01);
                unsigned a1l = packbf2(x02 - h02, x03 - h03);
                unsigned a2l = packbf2(x10 - h10, x11 - h11);
                unsigned a3l = packbf2(x12 - h12, x13 - h13);
                const uint2* w0p = Wc + (pp + tig) * SY;
                const uint2* w1p = Wc + (pp + tig + 4) * SY;
                #pragma unroll
                for (int nti = 0; nti < 8; nti++) {
                    int nb = (nh * 8 + nti) * 8 + gid;
                    uint2 b0 = w0p[nb], b1 = w1p[nb];
                    MMA_BF16(acc[nti], a0l, a1l, a2l, a3l, b0.x, b1.x);
                    MMA_BF16(acc[nti], a0h, a1h, a2h, a3h, b0.y, b1.y);
                    MMA_BF16(acc[nti], a0h, a1h, a2h, a3h, b0.x, b1.x);
                }
            }
        }
        __syncthreads();
        #pragma unroll
        for (int nti = 0; nti < 8; nti++) {
            int c0 = (nh * 8 + nti) * 8 + tig * 2;
            Yout[c0 * SY + mi] = leakyf(acc[nti][0]);
            Yout[(c0 + 1) * SY + mi] = leakyf(acc[nti][1]);
            Yout[c0 * SY + mi + 8] = leakyf(acc[nti][2]);
            Yout[(c0 + 1) * SY + mi + 8] = leakyf(acc[nti][3]);
        }
    }
    __syncthreads();

    {
        int col = tid >> 2, cq = tid & 3;
        float hj[8];
        #pragma unroll
        for (int j = 0; j < 8; j++) hj[j] = h2s[col * 8 + j];
        #pragma unroll 4
        for (int cc = 0; cc < 32; cc++) {
            int c = cq * 32 + cc;
            float s = sb2[c];
            #pragma unroll
            for (int j = 0; j < 8; j++) s += sw2[c * 8 + j] * hj[j];
            Xbuf[col * SY + c] = fmaxf(s, 0.f);
        }
    }
    __syncthreads();

    for (int e = tid; e < 1024; e += 512) {
        int pt = e >> 7, c = e & 127;
        const float* yr = Ybuf + c * SY + pt * 16;
        const float* sc = Xbuf + (pt * 16) * SY + c;
        float a = 0.f;
        #pragma unroll
        for (int k = 0; k < 16; k++) a += sc[k * SY] * yr[k];
        g_p2p[(size_t)(base + pt) * CO + c] = a;
    }
}

// ---------------- patch aggregation ----------------
__global__ void __launch_bounds__(128) k_patch(
    const float* __restrict__ n2w0, const float* __restrict__ n2b0,
    const float* __restrict__ n2w1, const float* __restrict__ n2b1,
    const float* __restrict__ n2w2, const float* __restrict__ n2b2,
    float* __restrict__ out)
{
    __shared__ float h2s[16][8];
    __shared__ int js[16];
    int q = blockIdx.x;
    int b = q / N1, n = q % N1;
    int tid = threadIdx.x;
    if (tid < 16) {
        int j = g_idx2[q * KN + tid];
        js[tid] = j;
        float dx0 = g_x1T[(b * N1 + j) * 3 + 0] - g_x1T[q * 3 + 0];
        float dx1 = g_x1T[(b * N1 + j) * 3 + 1] - g_x1T[q * 3 + 1];
        float dx2 = g_x1T[(b * N1 + j) * 3 + 2] - g_x1T[q * 3 + 2];
        float h[8];
        #pragma unroll
        for (int jj = 0; jj < 8; jj++) {
            float s = n2w0[jj * 3 + 0] * dx0 + n2w0[jj * 3 + 1] * dx1 + n2w0[jj * 3 + 2] * dx2 + n2b0[jj];
            h[jj] = fmaxf(s, 0.f);
        }
        #pragma unroll
        for (int jj = 0; jj < 8; jj++) {
            float s = n2b1[jj];
            #pragma unroll
            for (int m = 0; m < 8; m++) s += n2w1[jj * 8 + m] * h[m];
            h2s[tid][jj] = fmaxf(s, 0.f);
        }
    }
    __syncthreads();
    int c = tid;
    float w2r[8];
    #pragma unroll
    for (int j = 0; j < 8; j++) w2r[j] = n2w2[c * 8 + j];
    float bc = n2b2[c];
    float acc = 0.f;
    #pragma unroll
    for (int k = 0; k < KN; k++) {
        float s = bc;
        #pragma unroll
        for (int j = 0; j < 8; j++) s += w2r[j] * h2s[k][j];
        s = fmaxf(s, 0.f);
        acc += s * g_p2p[((size_t)b * N1 + js[k]) * CO + c];
    }
    out[(size_t)b * CO * N1 + (size_t)c * N1 + n] = acc;
}

// ---------------- launch ----------------
extern "C" void kernel_launch(void* const* d_in, const int* in_sizes, int n_in,
                              void* d_out, int out_size)
{
    int s = (n_in >= 31) ? 0 : -2;
    const float* xyz1 = (const float*)d_in[0];
    const float* xyz2 = (const float*)d_in[1];
    const float* pts1 = (const float*)d_in[2];
    const float* pts2 = (const float*)d_in[3];
    const float* vel1 = (const float*)d_in[4];
    const float* fcc  = (const float*)d_in[8 + s];
    const float* fcv  = (const float*)d_in[9 + s];
    const float* wxyz = (const float*)d_in[10 + s];
    const float* wpts = (const float*)d_in[12 + s];
    const float* mw0 = (const float*)d_in[13 + s];
    const float* mb0 = (const float*)d_in[14 + s];
    const float* mw1 = (const float*)d_in[15 + s];
    const float* mb1 = (const float*)d_in[16 + s];
    const float* mw2 = (const float*)d_in[17 + s];
    const float* mb2 = (const float*)d_in[18 + s];
    const float* n1w0 = (const float*)d_in[19 + s];
    const float* n1b0 = (const float*)d_in[20 + s];
    const float* n2w0 = (const float*)d_in[21 + s];
    const float* n2b0 = (const float*)d_in[22 + s];
    const float* n1w1 = (const float*)d_in[23 + s];
    const float* n1b1 = (const float*)d_in[24 + s];
    const float* n2w1 = (const float*)d_in[25 + s];
    const float* n2b1 = (const float*)d_in[26 + s];
    const float* n1w2 = (const float*)d_in[27 + s];
    const float* n1b2 = (const float*)d_in[28 + s];
    const float* n2w2 = (const float*)d_in[29 + s];
    const float* n2b2 = (const float*)d_in[30 + s];

    float* out = (float*)d_out;
    const int patch_elems = BATCH * CO * N1;
    const int vw_elems = BATCH * N1 * 3;
    float* out_vw = (out_size >= patch_elems + vw_elems) ? (out + patch_elems) : nullptr;

    cudaFuncSetAttribute(k_mlp_tc, cudaFuncAttributeMaxDynamicSharedMemorySize, (int)MLP2_SMEM);
    cudaFuncSetAttribute(k_dist_tc, cudaFuncAttributeMaxDynamicSharedMemorySize, (int)DIST_SMEM);

    const int prep_total = 2 * BATCH * CP * N1 + 2 * BATCH * 3 * N1;
    dim3 gg(N2 / 128, N1 / 128, BATCH);
    dim3 gt(N1 / 32, 2 * BATCH * 2);

    // order: topk0 is the 4th launch -> ncu lands on the top-k
    k_prep<<<(prep_total + 255) / 256, 256>>>(xyz1, xyz2, pts1, pts2, wxyz, wpts);
    k_normsAB<<<(BATCH * 4096 + 127) / 128, 128>>>();
    k_dist_tc<<<gg, 256, DIST_SMEM>>>(0);
    k_topk<<<BATCH * N1, 256>>>(0);
    k_rigid<<<(BATCH * N1 + 127) / 128, 128>>>(xyz1, vel1, fcc, fcv, out_vw);
    k_nc<<<(BATCH * N1 + 127) / 128, 128>>>();
    k_transp<<<gt, 256>>>(pts1, pts2);
    k_wprep<<<108, 256>>>(mw0, mw1, mw2);
    k_mlp_tc<<<(BATCH * N1) / TNP, 512, MLP2_SMEM>>>(mb0, mb1, mb2,
                                                     n1w0, n1b0, n1w1, n1b1, n1w2, n1b2);
    k_comb<<<(BATCH * CP * N1 + 255) / 256, 256>>>();
    k_dist_tc<<<gg, 256, DIST_SMEM>>>(1);
    k_topk<<<BATCH * N1, 256>>>(1);
    k_patch<<<BATCH * N1, 128>>>(n2w0, n2b0, n2w1, n2b1, n2w2, n2b2, out);
}

// round 13
// speedup vs baseline: 1.0819x; 1.0189x over previous
#include <cuda_runtime.h>
#include <cuda_bf16.h>
#include <math.h>

#define BATCH 2
#define N1 4096
#define N2 4096
#define DD 64
#define KN 16
#define KCC 8
#define CP 80      // padded feature channels (67 / 70 used)
#define CO 128

// ---------------- scratch (static device memory; no runtime alloc) ----------------
__device__ float g_dist[(size_t)BATCH * N1 * N2];        // 134 MB
__device__ float g_F1[BATCH * CP * N1];
__device__ float g_F2[BATCH * CP * N2];
__device__ float g_CB[BATCH * CP * N1];
__device__ float g_nA[BATCH * N1];
__device__ float g_nB[BATCH * N2];
__device__ float g_nC[BATCH * N1];
__device__ int   g_idx1[BATCH * N1 * KN];
__device__ int   g_idx2[BATCH * N1 * KN];
__device__ float g_vw[BATCH * N1 * 3];
__device__ float g_wf[BATCH * N1];
__device__ float g_wr[BATCH * N1];
__device__ float g_p1T[BATCH * N1 * DD];
__device__ float g_p2T[BATCH * N2 * DD];
__device__ float g_x1T[BATCH * N1 * 3];
__device__ float g_x2T[BATCH * N2 * 3];
__device__ float g_p2p[(size_t)BATCH * N1 * CO];
__device__ uint2 g_wbf[3][72][128];     // bf16 hi/lo split, transposed MLP weights (k-pairs)

__device__ __forceinline__ float leakyf(float x) { return x >= 0.f ? x : 0.1f * x; }
__device__ __forceinline__ unsigned long long u64min(unsigned long long a, unsigned long long b) {
    return a < b ? a : b;
}

// ---- tf32 helpers (dist kernel) ----
__device__ __forceinline__ float f2tf32f(float x) {
    unsigned int r;
    asm("cvt.rna.tf32.f32 %0, %1;" : "=r"(r) : "f"(x));
    return __uint_as_float(r);
}

#define MMA_TF32(acc, A0, A1, A2, A3, B0, B1)                                   \
    asm volatile("mma.sync.aligned.m16n8k8.row.col.f32.tf32.tf32.f32 "          \
                 "{%0,%1,%2,%3}, {%4,%5,%6,%7}, {%8,%9}, {%0,%1,%2,%3};"        \
                 : "+f"(acc[0]), "+f"(acc[1]), "+f"(acc[2]), "+f"(acc[3])       \
                 : "r"(__float_as_uint(A0)), "r"(__float_as_uint(A1)),          \
                   "r"(__float_as_uint(A2)), "r"(__float_as_uint(A3)),          \
                   "r"(__float_as_uint(B0)), "r"(__float_as_uint(B1)))

// ---- bf16 helpers (mlp kernel) ----
__device__ __forceinline__ float bf16_trunc(float x) {          // exact split: top 16 bits
    return __uint_as_float(__float_as_uint(x) & 0xffff0000u);
}
__device__ __forceinline__ unsigned packbf2(float lo_elem, float hi_elem) {
    __nv_bfloat162 v = __floats2bfloat162_rn(lo_elem, hi_elem); // .x = first arg (low half)
    return *(unsigned*)&v;
}

#define MMA_BF16(acc, A0, A1, A2, A3, B0, B1)                                   \
    asm volatile("mma.sync.aligned.m16n8k16.row.col.f32.bf16.bf16.f32 "         \
                 "{%0,%1,%2,%3}, {%4,%5,%6,%7}, {%8,%9}, {%0,%1,%2,%3};"        \
                 : "+f"(acc[0]), "+f"(acc[1]), "+f"(acc[2]), "+f"(acc[3])       \
                 : "r"(A0), "r"(A1), "r"(A2), "r"(A3), "r"(B0), "r"(B1))

// ---------------- rigid 3x3 least squares + mask ----------------
__global__ void k_rigid(const float* __restrict__ xyz1, const float* __restrict__ vel1,
                        const float* __restrict__ fcc, const float* __restrict__ fcv,
                        float* __restrict__ out_vw)
{
    int t = blockIdx.x * blockDim.x + threadIdx.x;
    if (t >= BATCH * N1) return;
    int b = t / N1, n = t % N1;
    const float* cc = fcc + (size_t)t * KCC * 3;
    const float* cv = fcv + (size_t)t * KCC;
    double A00 = 1e-6, A01 = 0, A02 = 0, A11 = 1e-6, A12 = 0, A22 = 1e-6;
    double r0 = 0, r1 = 0, r2 = 0;
    for (int k = 0; k < KCC; k++) {
        double x = cc[k * 3 + 0], y = cc[k * 3 + 1], z = cc[k * 3 + 2];
        double inv = 1.0 / sqrt(x * x + y * y + z * z);
        x *= inv; y *= inv; z *= inv;
        A00 += x * x; A01 += x * y; A02 += x * z;
        A11 += y * y; A12 += y * z; A22 += z * z;
        double v = (double)cv[k];
        r0 += x * v; r1 += y * v; r2 += z * v;
    }
    double c00 = A11 * A22 - A12 * A12;
    double c01 = A01 * A22 - A12 * A02;
    double c02 = A01 * A12 - A11 * A02;
    double det = A00 * c00 - A01 * c01 + A02 * c02;
    double id = 1.0 / det;
    double v0 = (r0 * c00 - A01 * (r1 * A22 - A12 * r2) + A02 * (r1 * A12 - A11 * r2)) * id;
    double v1 = (A00 * (r1 * A22 - A12 * r2) - r0 * c01 + A02 * (A01 * r2 - r1 * A02)) * id;
    double v2 = (A00 * (A11 * r2 - r1 * A12) - A01 * (A01 * r2 - r1 * A02) + r0 * c02) * id;

    float fx = xyz1[(b * 3 + 0) * N1 + n];
    float fy = xyz1[(b * 3 + 1) * N1 + n];
    float fz = xyz1[(b * 3 + 2) * N1 + n];
    double inl = 1.0 / sqrt((double)fx * fx + (double)fy * fy + (double)fz * fz);
    double err = fabs((v0 * fx + v1 * fy + v2 * fz) * inl - (double)vel1[t]);
    bool m = (err <= 5.0);
    g_wf[t] = m ? 0.1f : 0.9f;
    g_wr[t] = m ? 0.9f : 0.1f;
    g_vw[t * 3 + 0] = (float)v0;
    g_vw[t * 3 + 1] = (float)v1;
    g_vw[t * 3 + 2] = (float)v2;
    if (out_vw) {
        out_vw[t * 3 + 0] = (float)v0;
        out_vw[t * 3 + 1] = (float)v1;
        out_vw[t * 3 + 2] = (float)v2;
    }
}

// ---------------- fused: weighted feature build + xyz transposes ----------------
__global__ void k_prep(const float* __restrict__ xyz1, const float* __restrict__ xyz2,
                       const float* __restrict__ pts1, const float* __restrict__ pts2,
                       const float* __restrict__ wxyz_p, const float* __restrict__ wpts_p)
{
    float wx = *wxyz_p, wp = *wpts_p;
    const int totalF = BATCH * CP * N1;
    const int tx3 = BATCH * 3 * N1;
    const int total = 2 * totalF + 2 * tx3;
    for (int e = blockIdx.x * blockDim.x + threadIdx.x; e < total;
         e += gridDim.x * blockDim.x) {
        if (e < 2 * totalF) {
            int which = e / totalF;
            int r = e % totalF;
            int b = r / (CP * N1);
            int c = (r / N1) % CP;
            int n = r % N1;
            const float* xyz = which ? xyz2 : xyz1;
            const float* pts = which ? pts2 : pts1;
            float* F = which ? g_F2 : g_F1;
            float v = 0.f;
            if (c < 3) v = wx * xyz[(b * 3 + c) * N1 + n];
            else if (c < 67) v = wp * pts[(b * DD + (c - 3)) * N1 + n];
            F[r] = v;
        } else {
            int r = e - 2 * totalF;
            if (r < tx3) {
                int b = r / (3 * N1), c = (r / N1) % 3, n = r % N1;
                g_x1T[(b * N1 + n) * 3 + c] = xyz1[r];
            } else {
                r -= tx3;
                int b = r / (3 * N1), c = (r / N1) % 3, n = r % N1;
                g_x2T[(b * N2 + n) * 3 + c] = xyz2[r];
            }
        }
    }
}

// ---------------- MLP weight transpose + bf16 hi/lo split (runs once) ----------------
__global__ void k_wprep(const float* __restrict__ w0, const float* __restrict__ w1,
                        const float* __restrict__ w2)
{
    const int per = 72 * 128;
    for (int e = blockIdx.x * blockDim.x + threadIdx.x; e < 3 * per;
         e += gridDim.x * blockDim.x) {
        int l = e / per;
        int r = e % per;
        int kp = r >> 7, c = r & 127;
        int KD = (l == 0) ? 131 : 128;
        const float* w = (l == 0) ? w0 : (l == 1) ? w1 : w2;
        int k0 = 2 * kp, k1 = 2 * kp + 1;
        float v0 = (k0 < KD) ? w[c * KD + k0] : 0.f;
        float v1 = (k1 < KD) ? w[c * KD + k1] : 0.f;
        float h0 = bf16_trunc(v0), h1 = bf16_trunc(v1);
        uint2 o;
        o.x = packbf2(h0, h1);
        o.y = packbf2(v0 - h0, v1 - h1);
        g_wbf[l][kp][c] = o;
    }
}

// ---------------- coalesced tiled transpose: [B][C][N] -> [B][N][C], C=64 ----------------
__global__ void __launch_bounds__(256) k_transp(const float* __restrict__ src1,
                                                const float* __restrict__ src2)
{
    __shared__ float t[32][33];
    int zc = blockIdx.y;
    int ct = zc & 1;
    int b = (zc >> 1) & (BATCH - 1);
    int which = zc >> 2;
    const float* src = which ? src2 : src1;
    float* dst = which ? g_p2T : g_p1T;
    int n0 = blockIdx.x * 32;
    int c0 = ct * 32;
    int lx = threadIdx.x & 31, ly = threadIdx.x >> 5;
    #pragma unroll
    for (int r = 0; r < 4; r++) {
        int c = c0 + ly + r * 8;
        t[ly + r * 8][lx] = src[((size_t)b * DD + c) * N1 + n0 + lx];
    }
    __syncthreads();
    #pragma unroll
    for (int r = 0; r < 4; r++) {
        int n = n0 + ly + r * 8;
        dst[((size_t)b * N1 + n) * DD + c0 + lx] = t[lx][ly + r * 8];
    }
}

// ---------------- fused: norms A/B + comb features + comb norm (needs rigid) ----------------
__global__ void k_normsComb()
{
    int t = blockIdx.x * blockDim.x + threadIdx.x;
    if (t >= BATCH * 4096) return;
    int b = t / 4096, n = t % 4096;
    float wf = g_wf[t], wr = g_wr[t];
    float v0 = g_vw[t * 3 + 0], v1 = g_vw[t * 3 + 1], v2 = g_vw[t * 3 + 2];
    float sA = 0.f, sB = 0.f;
    #pragma unroll 8
    for (int c = 0; c < CP; c++) {
        float a = g_F1[(b * CP + c) * 4096 + n];
        float bb = g_F2[(b * CP + c) * 4096 + n];
        sA += a * a;
        sB += bb * bb;
        float cv = 0.f;
        if (c < 67) cv = wf * a;
        else if (c == 67) cv = wr * v0;
        else if (c == 68) cv = wr * v1;
        else if (c == 69) cv = wr * v2;
        g_CB[(b * CP + c) * 4096 + n] = cv;
    }
    g_nA[t] = sA;
    g_nB[t] = sB;
    g_nC[t] = wf * wf * sA + wr * wr * (v0 * v0 + v1 * v1 + v2 * v2);
}

// ---------------- distance GEMM on tensor cores (3xTF32, hi/lo interleaved) ----------------
// CPK=40 (2 chunks) — measured-best configuration (128.6 us)
#define CPK 40
#define S2 132
#define SLAB2 (CPK * S2)
#define DIST_SMEM ((2 * SLAB2 * 2 + 256) * 4)

__global__ void __launch_bounds__(256) k_dist_tc(int sel)
{
    extern __shared__ float2 dsm2[];
    float2* As2 = dsm2;                 // [CPK][S2] (hi,lo)
    float2* Bs2 = As2 + SLAB2;
    float* nAs = (float*)(Bs2 + SLAB2); // 128
    float* nBs = nAs + 128;             // 128

    const float* FA = sel ? g_CB : g_F1;
    const float* FB = sel ? g_CB : g_F2;
    const float* nAv = sel ? g_nC : g_nA;
    const float* nBv = sel ? g_nC : g_nB;

    int b = blockIdx.z;
    int i0 = blockIdx.y * 128, j0 = blockIdx.x * 128;
    const float* Asrc = FA + (size_t)b * CP * N1 + i0;
    const float* Bsrc = FB + (size_t)b * CP * N2 + j0;

    int tid = threadIdx.x;
    if (tid < 128) {
        nAs[tid] = nAv[b * N1 + i0 + tid];
        nBs[tid] = nBv[b * N2 + j0 + tid];
    }

    int warp = tid >> 5, lane = tid & 31;
    int gid = lane >> 2, tig = lane & 3;
    int mi = warp * 16 + gid;

    float acc[16][4];
    #pragma unroll
    for (int nt = 0; nt < 16; nt++)
        #pragma unroll
        for (int u = 0; u < 4; u++) acc[nt][u] = 0.f;

    for (int kb = 0; kb < CP; kb += CPK) {
        for (int idx = tid; idx < CPK * 32 * 2; idx += 256) {
            int which = idx >= CPK * 32;
            int r = which ? idx - CPK * 32 : idx;
            int k = r >> 5, c4 = (r & 31) << 2;
            const float* src = which ? Bsrc : Asrc;
            float2* dst = (which ? Bs2 : As2) + k * S2 + c4;
            float4 v = *(const float4*)(src + (size_t)(kb + k) * 4096 + c4);
            float h;
            h = f2tf32f(v.x); dst[0] = make_float2(h, f2tf32f(v.x - h));
            h = f2tf32f(v.y); dst[1] = make_float2(h, f2tf32f(v.y - h));
            h = f2tf32f(v.z); dst[2] = make_float2(h, f2tf32f(v.z - h));
            h = f2tf32f(v.w); dst[3] = make_float2(h, f2tf32f(v.w - h));
        }
        __syncthreads();

        #pragma unroll
        for (int kk = 0; kk < CPK; kk += 8) {
            const float2* r0 = As2 + (kk + tig) * S2;
            const float2* r1 = As2 + (kk + tig + 4) * S2;
            float2 a0 = r0[mi], a1 = r0[mi + 8];
            float2 a2 = r1[mi], a3 = r1[mi + 8];
            const float2* q0 = Bs2 + (kk + tig) * S2;
            const float2* q1 = Bs2 + (kk + tig + 4) * S2;
            #pragma unroll
            for (int nt = 0; nt < 16; nt++) {
                int nb = nt * 8 + gid;
                float2 b0 = q0[nb], b1 = q1[nb];
                MMA_TF32(acc[nt], a0.y, a1.y, a2.y, a3.y, b0.x, b1.x);  // lo*hi
                MMA_TF32(acc[nt], a0.x, a1.x, a2.x, a3.x, b0.y, b1.y);  // hi*lo
                MMA_TF32(acc[nt], a0.x, a1.x, a2.x, a3.x, b0.x, b1.x);  // hi*hi
            }
        }
        __syncthreads();
    }

    float* drow = g_dist + (size_t)b * N1 * N2;
    float ni0 = nAs[mi], ni1 = nAs[mi + 8];
    size_t ro0 = (size_t)(i0 + mi) * N2 + j0;
    size_t ro1 = ro0 + (size_t)8 * N2;
    #pragma unroll
    for (int nt = 0; nt < 16; nt++) {
        int jc = nt * 8 + tig * 2;
        float nj0 = nBs[jc], nj1 = nBs[jc + 1];
        float2 o0, o1;
        o0.x = fmaxf(ni0 - 2.f * acc[nt][0] + nj0, 0.f);
        o0.y = fmaxf(ni0 - 2.f * acc[nt][1] + nj1, 0.f);
        o1.x = fmaxf(ni1 - 2.f * acc[nt][2] + nj0, 0.f);
        o1.y = fmaxf(ni1 - 2.f * acc[nt][3] + nj1, 0.f);
        *(float2*)(drow + ro0 + jc) = o0;
        *(float2*)(drow + ro1 + jc) = o1;
    }
}

// ---------------- top-K v5: 4 rows/block, 4 concurrent extraction warps ----------------
#define RPB 4
__global__ void __launch_bounds__(256) k_topk(int sel)
{
    __shared__ unsigned long long segmin[RPB][256];   // 8 KB
    int q0 = blockIdx.x * RPB;
    int* idxo = sel ? g_idx2 : g_idx1;
    int tid = threadIdx.x;

    // build: thread tid computes min key of segment tid for each of RPB rows
    #pragma unroll
    for (int rr = 0; rr < RPB; rr++) {
        const float* row = g_dist + (size_t)(q0 + rr) * N2;
        int basej = tid * 16;
        float mv = __int_as_float(0x7f7fffff);   // FLT_MAX
        int mj = basej;
        #pragma unroll
        for (int i = 0; i < 4; i++) {
            float4 f = *(const float4*)(row + basej + i * 4);
            int j0 = basej + i * 4;
            if (f.x < mv) { mv = f.x; mj = j0 + 0; }
            if (f.y < mv) { mv = f.y; mj = j0 + 1; }
            if (f.z < mv) { mv = f.z; mj = j0 + 2; }
            if (f.w < mv) { mv = f.w; mj = j0 + 3; }
        }
        segmin[rr][tid] = ((unsigned long long)__float_as_uint(mv) << 32) | (unsigned)mj;
    }
    __syncthreads();

    // extraction: warps 0..RPB-1 each own one row
    int w = tid >> 5, lane = tid & 31;
    if (w < RPB) {
        int q = q0 + w;
        const float* row = g_dist + (size_t)q * N2;
        unsigned long long r[8];
        #pragma unroll
        for (int i = 0; i < 8; i++) r[i] = segmin[w][lane + 32 * i];
        int ex[KN];
        #pragma unroll
        for (int i = 0; i < KN; i++) ex[i] = -1;

        for (int k = 0; k < KN; k++) {
            unsigned long long m = r[0];
            #pragma unroll
            for (int i = 1; i < 8; i++) m = u64min(m, r[i]);
            #pragma unroll
            for (int o = 16; o; o >>= 1)
                m = u64min(m, __shfl_xor_sync(0xffffffffu, m, o));
            int j = (int)(unsigned)(m & 0xffffffffULL);
            #pragma unroll
            for (int i = 0; i < KN; i++) if (i == k) ex[i] = j;
            if (lane == 0) idxo[q * KN + k] = j;
            if (k == KN - 1) break;

            // rescan winning segment from gmem (L2-hot), masking extracted indices
            int seg = j >> 4;
            unsigned long long v = ~0ull;
            if (lane < 16) {
                int idx = seg * 16 + lane;
                float f = __ldg(row + idx);
                v = ((unsigned long long)__float_as_uint(f) << 32) | (unsigned)idx;
                #pragma unroll
                for (int i = 0; i < KN; i++)
                    if (i <= k && ex[i] == idx) v = ~0ull;
            }
            #pragma unroll
            for (int o = 8; o; o >>= 1)
                v = u64min(v, __shfl_xor_sync(0xffffffffu, v, o));
            unsigned long long vb = __shfl_sync(0xffffffffu, v, 0);
            int slot = seg >> 5, ln = seg & 31;
            #pragma unroll
            for (int i = 0; i < 8; i++)
                if (i == slot && lane == ln) r[i] = vb;
        }
    }
}

// ---------------- fused MLP on tensor cores (bf16 3-term split, m16n8k16) ----------------
#define TNP 8
#define SY 132
#define MX   0
#define MYO  (144 * SY)
#define MWC  (MYO + 128 * SY)
#define MB   (MWC + 24 * SY * 2)
#define MH2  (MB + 384)
#define MSW2 (MH2 + 1024)
#define MSB2 (MSW2 + 1024)
#define MIDX (MSB2 + 128)
#define MLP2_SMEM ((MIDX + 128) * 4)

__global__ void __launch_bounds__(512) k_mlp_tc(
    const float* __restrict__ b0g, const float* __restrict__ b1g,
    const float* __restrict__ b2g,
    const float* __restrict__ n1w0, const float* __restrict__ n1b0,
    const float* __restrict__ n1w1, const float* __restrict__ n1b1,
    const float* __restrict__ n1w2, const float* __restrict__ n1b2)
{
    extern __shared__ float sm[];
    float* Xbuf = sm + MX;
    float* Ybuf = sm + MYO;
    uint2* Wc = (uint2*)(sm + MWC);
    float* biasS = sm + MB;
    float* h2s = sm + MH2;
    float* sw2 = sm + MSW2;
    float* sb2 = sm + MSB2;
    int* idxs = (int*)(sm + MIDX);

    int tid = threadIdx.x;
    int warp = tid >> 5, lane = tid & 31;
    int gid = lane >> 2, tig = lane & 3;
    int wm = warp & 7, nh = warp >> 3;
    int mi = wm * 16 + gid;
    int base = blockIdx.x * TNP;

    if (tid < 128) {
        idxs[tid] = g_idx1[base * KN + tid];
        #pragma unroll
        for (int r = 0; r < 8; r++) sw2[tid + 128 * r] = n1w2[tid + 128 * r];
        sb2[tid] = n1b2[tid];
        biasS[tid] = b0g[tid];
        biasS[128 + tid] = b1g[tid];
        biasS[256 + tid] = b2g[tid];
    }
    __syncthreads();

    for (int e = tid; e < 144 * 128; e += 512) {
        int i = e >> 7, col = e & 127;
        int tn = col >> 4;
        int pt = base + tn;
        int b = pt >> 12;
        int j = idxs[col];
        float v;
        if (i < 64) v = g_p1T[(size_t)pt * DD + i];
        else if (i < 128) v = g_p2T[((size_t)b * N2 + j) * DD + (i - 64)];
        else if (i < 131) v = g_x2T[(b * N2 + j) * 3 + (i - 128)] - g_x1T[pt * 3 + (i - 128)];
        else v = 0.f;
        Xbuf[i * SY + col] = v;
    }
    __syncthreads();

    if (tid < 128) {
        int col = tid;
        float dx0 = Xbuf[128 * SY + col];
        float dx1 = Xbuf[129 * SY + col];
        float dx2 = Xbuf[130 * SY + col];
        float h[8];
        #pragma unroll
        for (int j = 0; j < 8; j++) {
            float s = n1w0[j * 3 + 0] * dx0 + n1w0[j * 3 + 1] * dx1 + n1w0[j * 3 + 2] * dx2 + n1b0[j];
            h[j] = fmaxf(s, 0.f);
        }
        #pragma unroll
        for (int j = 0; j < 8; j++) {
            float s = n1b1[j];
            #pragma unroll
            for (int m = 0; m < 8; m++) s += n1w1[j * 8 + m] * h[m];
            h2s[col * 8 + j] = fmaxf(s, 0.f);
        }
    }

    #pragma unroll 1
    for (int l = 0; l < 3; l++) {
        const int KPL = (l == 0) ? 72 : 64;
        const float* Xin = (l == 1) ? Ybuf : Xbuf;
        float* Yout = (l == 1) ? Xbuf : Ybuf;

        float acc[8][4];
        #pragma unroll
        for (int nti = 0; nti < 8; nti++) {
            int c0 = (nh * 8 + nti) * 8 + tig * 2;
            acc[nti][0] = biasS[l * 128 + c0];
            acc[nti][1] = biasS[l * 128 + c0 + 1];
            acc[nti][2] = acc[nti][0];
            acc[nti][3] = acc[nti][1];
        }

        for (int kbp = 0; kbp < KPL; kbp += 24) {
            int cs = (KPL - kbp < 24) ? (KPL - kbp) : 24;
            __syncthreads();
            for (int e = tid; e < cs * 128; e += 512) {
                int kl = e >> 7, c = e & 127;
                Wc[kl * SY + c] = g_wbf[l][kbp + kl][c];
            }
            __syncthreads();
            for (int pp = 0; pp < cs; pp += 8) {
                int kp0 = kbp + pp + tig;
                int kp1 = kp0 + 4;
                int r00 = 2 * kp0, r10 = 2 * kp1;
                float x00 = Xin[r00 * SY + mi];
                float x01 = Xin[(r00 + 1) * SY + mi];
                float x02 = Xin[r00 * SY + mi + 8];
                float x03 = Xin[(r00 + 1) * SY + mi + 8];
                float x10 = Xin[r10 * SY + mi];
                float x11 = Xin[(r10 + 1) * SY + mi];
                float x12 = Xin[r10 * SY + mi + 8];
                float x13 = Xin[(r10 + 1) * SY + mi + 8];
                float h00 = bf16_trunc(x00), h01 = bf16_trunc(x01);
                float h02 = bf16_trunc(x02), h03 = bf16_trunc(x03);
                float h10 = bf16_trunc(x10), h11 = bf16_trunc(x11);
                float h12 = bf16_trunc(x12), h13 = bf16_trunc(x13);
                unsigned a0h = packbf2(h00, h01), a1h = packbf2(h02, h03);
                unsigned a2h = packbf2(h10, h11), a3h = packbf2(h12, h13);
                unsigned a0l = packbf2(x00 - h00, x01 - h01);
                unsigned a1l = packbf2(x02 - h02, x03 - h03);
                unsigned a2l = packbf2(x10 - h10, x11 - h11);
                unsigned a3l = packbf2(x12 - h12, x13 - h13);
                const uint2* w0p = Wc + (pp + tig) * SY;
                const uint2* w1p = Wc + (pp + tig + 4) * SY;
                #pragma unroll
                for (int nti = 0; nti < 8; nti++) {
                    int nb = (nh * 8 + nti) * 8 + gid;
                    uint2 b0 = w0p[nb], b1 = w1p[nb];
                    MMA_BF16(acc[nti], a0l, a1l, a2l, a3l, b0.x, b1.x);
                    MMA_BF16(acc[nti], a0h, a1h, a2h, a3h, b0.y, b1.y);
                    MMA_BF16(acc[nti], a0h, a1h, a2h, a3h, b0.x, b1.x);
                }
            }
        }
        __syncthreads();
        #pragma unroll
        for (int nti = 0; nti < 8; nti++) {
            int c0 = (nh * 8 + nti) * 8 + tig * 2;
            Yout[c0 * SY + mi] = leakyf(acc[nti][0]);
            Yout[(c0 + 1) * SY + mi] = leakyf(acc[nti][1]);
            Yout[c0 * SY + mi + 8] = leakyf(acc[nti][2]);
            Yout[(c0 + 1) * SY + mi + 8] = leakyf(acc[nti][3]);
        }
    }
    __syncthreads();

    {
        int col = tid >> 2, cq = tid & 3;
        float hj[8];
        #pragma unroll
        for (int j = 0; j < 8; j++) hj[j] = h2s[col * 8 + j];
        #pragma unroll 4
        for (int cc = 0; cc < 32; cc++) {
            int c = cq * 32 + cc;
            float s = sb2[c];
            #pragma unroll
            for (int j = 0; j < 8; j++) s += sw2[c * 8 + j] * hj[j];
            Xbuf[col * SY + c] = fmaxf(s, 0.f);
        }
    }
    __syncthreads();

    for (int e = tid; e < 1024; e += 512) {
        int pt = e >> 7, c = e & 127;
        const float* yr = Ybuf + c * SY + pt * 16;
        const float* sc = Xbuf + (pt * 16) * SY + c;
        float a = 0.f;
        #pragma unroll
        for (int k = 0; k < 16; k++) a += sc[k * SY] * yr[k];
        g_p2p[(size_t)(base + pt) * CO + c] = a;
    }
}

// ---------------- patch aggregation ----------------
__global__ void __launch_bounds__(128) k_patch(
    const float* __restrict__ n2w0, const float* __restrict__ n2b0,
    const float* __restrict__ n2w1, const float* __restrict__ n2b1,
    const float* __restrict__ n2w2, const float* __restrict__ n2b2,
    float* __restrict__ out)
{
    __shared__ float h2s[16][8];
    __shared__ int js[16];
    int q = blockIdx.x;
    int b = q / N1, n = q % N1;
    int tid = threadIdx.x;
    if (tid < 16) {
        int j = g_idx2[q * KN + tid];
        js[tid] = j;
        float dx0 = g_x1T[(b * N1 + j) * 3 + 0] - g_x1T[q * 3 + 0];
        float dx1 = g_x1T[(b * N1 + j) * 3 + 1] - g_x1T[q * 3 + 1];
        float dx2 = g_x1T[(b * N1 + j) * 3 + 2] - g_x1T[q * 3 + 2];
        float h[8];
        #pragma unroll
        for (int jj = 0; jj < 8; jj++) {
            float s = n2w0[jj * 3 + 0] * dx0 + n2w0[jj * 3 + 1] * dx1 + n2w0[jj * 3 + 2] * dx2 + n2b0[jj];
            h[jj] = fmaxf(s, 0.f);
        }
        #pragma unroll
        for (int jj = 0; jj < 8; jj++) {
            float s = n2b1[jj];
            #pragma unroll
            for (int m = 0; m < 8; m++) s += n2w1[jj * 8 + m] * h[m];
            h2s[tid][jj] = fmaxf(s, 0.f);
        }
    }
    __syncthreads();
    int c = tid;
    float w2r[8];
    #pragma unroll
    for (int j = 0; j < 8; j++) w2r[j] = n2w2[c * 8 + j];
    float bc = n2b2[c];
    float acc = 0.f;
    #pragma unroll
    for (int k = 0; k < KN; k++) {
        float s = bc;
        #pragma unroll
        for (int j = 0; j < 8; j++) s += w2r[j] * h2s[k][j];
        s = fmaxf(s, 0.f);
        acc += s * g_p2p[((size_t)b * N1 + js[k]) * CO + c];
    }
    out[(size_t)b * CO * N1 + (size_t)c * N1 + n] = acc;
}

// ---------------- launch ----------------
extern "C" void kernel_launch(void* const* d_in, const int* in_sizes, int n_in,
                              void* d_out, int out_size)
{
    int s = (n_in >= 31) ? 0 : -2;
    const float* xyz1 = (const float*)d_in[0];
    const float* xyz2 = (const float*)d_in[1];
    const float* pts1 = (const float*)d_in[2];
    const float* pts2 = (const float*)d_in[3];
    const float* vel1 = (const float*)d_in[4];
    const float* fcc  = (const float*)d_in[8 + s];
    const float* fcv  = (const float*)d_in[9 + s];
    const float* wxyz = (const float*)d_in[10 + s];
    const float* wpts = (const float*)d_in[12 + s];
    const float* mw0 = (const float*)d_in[13 + s];
    const float* mb0 = (const float*)d_in[14 + s];
    const float* mw1 = (const float*)d_in[15 + s];
    const float* mb1 = (const float*)d_in[16 + s];
    const float* mw2 = (const float*)d_in[17 + s];
    const float* mb2 = (const float*)d_in[18 + s];
    const float* n1w0 = (const float*)d_in[19 + s];
    const float* n1b0 = (const float*)d_in[20 + s];
    const float* n2w0 = (const float*)d_in[21 + s];
    const float* n2b0 = (const float*)d_in[22 + s];
    const float* n1w1 = (const float*)d_in[23 + s];
    const float* n1b1 = (const float*)d_in[24 + s];
    const float* n2w1 = (const float*)d_in[25 + s];
    const float* n2b1 = (const float*)d_in[26 + s];
    const float* n1w2 = (const float*)d_in[27 + s];
    const float* n1b2 = (const float*)d_in[28 + s];
    const float* n2w2 = (const float*)d_in[29 + s];
    const float* n2b2 = (const float*)d_in[30 + s];

    float* out = (float*)d_out;
    const int patch_elems = BATCH * CO * N1;
    const int vw_elems = BATCH * N1 * 3;
    float* out_vw = (out_size >= patch_elems + vw_elems) ? (out + patch_elems) : nullptr;

    cudaFuncSetAttribute(k_mlp_tc, cudaFuncAttributeMaxDynamicSharedMemorySize, (int)MLP2_SMEM);
    cudaFuncSetAttribute(k_dist_tc, cudaFuncAttributeMaxDynamicSharedMemorySize, (int)DIST_SMEM);

    const int prep_total = 2 * BATCH * CP * N1 + 2 * BATCH * 3 * N1;
    dim3 gg(N2 / 128, N1 / 128, BATCH);
    dim3 gt(N1 / 32, 2 * BATCH * 2);

    k_rigid<<<(BATCH * N1 + 127) / 128, 128>>>(xyz1, vel1, fcc, fcv, out_vw);
    k_prep<<<(prep_total + 255) / 256, 256>>>(xyz1, xyz2, pts1, pts2, wxyz, wpts);
    k_normsComb<<<(BATCH * 4096 + 127) / 128, 128>>>();
    k_dist_tc<<<gg, 256, DIST_SMEM>>>(0);
    k_topk<<<BATCH * N1 / RPB, 256>>>(0);
    k_transp<<<gt, 256>>>(pts1, pts2);
    k_wprep<<<108, 256>>>(mw0, mw1, mw2);
    k_mlp_tc<<<(BATCH * N1) / TNP, 512, MLP2_SMEM>>>(mb0, mb1, mb2,
                                                     n1w0, n1b0, n1w1, n1b1, n1w2, n1b2);
    k_dist_tc<<<gg, 256, DIST_SMEM>>>(1);
    k_topk<<<BATCH * N1 / RPB, 256>>>(1);
    k_patch<<<BATCH * N1, 128>>>(n2w0, n2b0, n2w1, n2b1, n2w2, n2b2, out);
}

// round 14
// speedup vs baseline: 1.0981x; 1.0150x over previous
#include <cuda_runtime.h>
#include <cuda_bf16.h>
#include <math.h>

#define BATCH 2
#define N1 4096
#define N2 4096
#define DD 64
#define KN 16
#define KCC 8
#define CP 80      // padded feature channels (67 / 70 used)
#define CO 128

// ---------------- scratch (static device memory; no runtime alloc) ----------------
__device__ float g_dist[(size_t)BATCH * N1 * N2];        // 134 MB
__device__ float g_F1[BATCH * CP * N1];
__device__ float g_F2[BATCH * CP * N2];
__device__ float2 g_F1s[BATCH * CP * N1];   // tf32 hi/lo split
__device__ float2 g_F2s[BATCH * CP * N2];
__device__ float2 g_CBs[BATCH * CP * N1];
__device__ float g_nA[BATCH * N1];
__device__ float g_nB[BATCH * N2];
__device__ float g_nC[BATCH * N1];
__device__ int   g_idx1[BATCH * N1 * KN];
__device__ int   g_idx2[BATCH * N1 * KN];
__device__ float g_vw[BATCH * N1 * 3];
__device__ float g_wf[BATCH * N1];
__device__ float g_wr[BATCH * N1];
__device__ float g_p1T[BATCH * N1 * DD];
__device__ float g_p2T[BATCH * N2 * DD];
__device__ float g_x1T[BATCH * N1 * 3];
__device__ float g_x2T[BATCH * N2 * 3];
__device__ float g_p2p[(size_t)BATCH * N1 * CO];
__device__ uint2 g_wbf[3][72][128];     // bf16 hi/lo split, transposed MLP weights (k-pairs)

__device__ __forceinline__ float leakyf(float x) { return x >= 0.f ? x : 0.1f * x; }
__device__ __forceinline__ unsigned long long u64min(unsigned long long a, unsigned long long b) {
    return a < b ? a : b;
}

// ---- tf32 helpers (dist kernel) ----
__device__ __forceinline__ float f2tf32f(float x) {
    unsigned int r;
    asm("cvt.rna.tf32.f32 %0, %1;" : "=r"(r) : "f"(x));
    return __uint_as_float(r);
}
__device__ __forceinline__ float2 tf32split(float v) {
    float h = f2tf32f(v);
    return make_float2(h, f2tf32f(v - h));
}

#define MMA_TF32(acc, A0, A1, A2, A3, B0, B1)                                   \
    asm volatile("mma.sync.aligned.m16n8k8.row.col.f32.tf32.tf32.f32 "          \
                 "{%0,%1,%2,%3}, {%4,%5,%6,%7}, {%8,%9}, {%0,%1,%2,%3};"        \
                 : "+f"(acc[0]), "+f"(acc[1]), "+f"(acc[2]), "+f"(acc[3])       \
                 : "r"(__float_as_uint(A0)), "r"(__float_as_uint(A1)),          \
                   "r"(__float_as_uint(A2)), "r"(__float_as_uint(A3)),          \
                   "r"(__float_as_uint(B0)), "r"(__float_as_uint(B1)))

// ---- bf16 helpers (mlp kernel) ----
__device__ __forceinline__ float bf16_trunc(float x) {          // exact split: top 16 bits
    return __uint_as_float(__float_as_uint(x) & 0xffff0000u);
}
__device__ __forceinline__ unsigned packbf2(float lo_elem, float hi_elem) {
    __nv_bfloat162 v = __floats2bfloat162_rn(lo_elem, hi_elem);
    return *(unsigned*)&v;
}

#define MMA_BF16(acc, A0, A1, A2, A3, B0, B1)                                   \
    asm volatile("mma.sync.aligned.m16n8k16.row.col.f32.bf16.bf16.f32 "         \
                 "{%0,%1,%2,%3}, {%4,%5,%6,%7}, {%8,%9}, {%0,%1,%2,%3};"        \
                 : "+f"(acc[0]), "+f"(acc[1]), "+f"(acc[2]), "+f"(acc[3])       \
                 : "r"(A0), "r"(A1), "r"(A2), "r"(A3), "r"(B0), "r"(B1))

// ---------------- rigid 3x3 least squares + mask ----------------
__global__ void k_rigid(const float* __restrict__ xyz1, const float* __restrict__ vel1,
                        const float* __restrict__ fcc, const float* __restrict__ fcv,
                        float* __restrict__ out_vw)
{
    int t = blockIdx.x * blockDim.x + threadIdx.x;
    if (t >= BATCH * N1) return;
    int b = t / N1, n = t % N1;
    const float* cc = fcc + (size_t)t * KCC * 3;
    const float* cv = fcv + (size_t)t * KCC;
    double A00 = 1e-6, A01 = 0, A02 = 0, A11 = 1e-6, A12 = 0, A22 = 1e-6;
    double r0 = 0, r1 = 0, r2 = 0;
    for (int k = 0; k < KCC; k++) {
        double x = cc[k * 3 + 0], y = cc[k * 3 + 1], z = cc[k * 3 + 2];
        double inv = 1.0 / sqrt(x * x + y * y + z * z);
        x *= inv; y *= inv; z *= inv;
        A00 += x * x; A01 += x * y; A02 += x * z;
        A11 += y * y; A12 += y * z; A22 += z * z;
        double v = (double)cv[k];
        r0 += x * v; r1 += y * v; r2 += z * v;
    }
    double c00 = A11 * A22 - A12 * A12;
    double c01 = A01 * A22 - A12 * A02;
    double c02 = A01 * A12 - A11 * A02;
    double det = A00 * c00 - A01 * c01 + A02 * c02;
    double id = 1.0 / det;
    double v0 = (r0 * c00 - A01 * (r1 * A22 - A12 * r2) + A02 * (r1 * A12 - A11 * r2)) * id;
    double v1 = (A00 * (r1 * A22 - A12 * r2) - r0 * c01 + A02 * (A01 * r2 - r1 * A02)) * id;
    double v2 = (A00 * (A11 * r2 - r1 * A12) - A01 * (A01 * r2 - r1 * A02) + r0 * c02) * id;

    float fx = xyz1[(b * 3 + 0) * N1 + n];
    float fy = xyz1[(b * 3 + 1) * N1 + n];
    float fz = xyz1[(b * 3 + 2) * N1 + n];
    double inl = 1.0 / sqrt((double)fx * fx + (double)fy * fy + (double)fz * fz);
    double err = fabs((v0 * fx + v1 * fy + v2 * fz) * inl - (double)vel1[t]);
    bool m = (err <= 5.0);
    g_wf[t] = m ? 0.1f : 0.9f;
    g_wr[t] = m ? 0.9f : 0.1f;
    g_vw[t * 3 + 0] = (float)v0;
    g_vw[t * 3 + 1] = (float)v1;
    g_vw[t * 3 + 2] = (float)v2;
    if (out_vw) {
        out_vw[t * 3 + 0] = (float)v0;
        out_vw[t * 3 + 1] = (float)v1;
        out_vw[t * 3 + 2] = (float)v2;
    }
}

// ---------------- fused: weighted feature build (fp32 + tf32 split) + xyz transposes ----------------
__global__ void k_prep(const float* __restrict__ xyz1, const float* __restrict__ xyz2,
                       const float* __restrict__ pts1, const float* __restrict__ pts2,
                       const float* __restrict__ wxyz_p, const float* __restrict__ wpts_p)
{
    float wx = *wxyz_p, wp = *wpts_p;
    const int totalF = BATCH * CP * N1;
    const int tx3 = BATCH * 3 * N1;
    const int total = 2 * totalF + 2 * tx3;
    for (int e = blockIdx.x * blockDim.x + threadIdx.x; e < total;
         e += gridDim.x * blockDim.x) {
        if (e < 2 * totalF) {
            int which = e / totalF;
            int r = e % totalF;
            int b = r / (CP * N1);
            int c = (r / N1) % CP;
            int n = r % N1;
            const float* xyz = which ? xyz2 : xyz1;
            const float* pts = which ? pts2 : pts1;
            float v = 0.f;
            if (c < 3) v = wx * xyz[(b * 3 + c) * N1 + n];
            else if (c < 67) v = wp * pts[(b * DD + (c - 3)) * N1 + n];
            if (which) { g_F2[r] = v; g_F2s[r] = tf32split(v); }
            else       { g_F1[r] = v; g_F1s[r] = tf32split(v); }
        } else {
            int r = e - 2 * totalF;
            if (r < tx3) {
                int b = r / (3 * N1), c = (r / N1) % 3, n = r % N1;
                g_x1T[(b * N1 + n) * 3 + c] = xyz1[r];
            } else {
                r -= tx3;
                int b = r / (3 * N1), c = (r / N1) % 3, n = r % N1;
                g_x2T[(b * N2 + n) * 3 + c] = xyz2[r];
            }
        }
    }
}

// ---------------- MLP weight transpose + bf16 hi/lo split (runs once) ----------------
__global__ void k_wprep(const float* __restrict__ w0, const float* __restrict__ w1,
                        const float* __restrict__ w2)
{
    const int per = 72 * 128;
    for (int e = blockIdx.x * blockDim.x + threadIdx.x; e < 3 * per;
         e += gridDim.x * blockDim.x) {
        int l = e / per;
        int r = e % per;
        int kp = r >> 7, c = r & 127;
        int KD = (l == 0) ? 131 : 128;
        const float* w = (l == 0) ? w0 : (l == 1) ? w1 : w2;
        int k0 = 2 * kp, k1 = 2 * kp + 1;
        float v0 = (k0 < KD) ? w[c * KD + k0] : 0.f;
        float v1 = (k1 < KD) ? w[c * KD + k1] : 0.f;
        float h0 = bf16_trunc(v0), h1 = bf16_trunc(v1);
        uint2 o;
        o.x = packbf2(h0, h1);
        o.y = packbf2(v0 - h0, v1 - h1);
        g_wbf[l][kp][c] = o;
    }
}

// ---------------- coalesced tiled transpose: [B][C][N] -> [B][N][C], C=64 ----------------
__global__ void __launch_bounds__(256) k_transp(const float* __restrict__ src1,
                                                const float* __restrict__ src2)
{
    __shared__ float t[32][33];
    int zc = blockIdx.y;
    int ct = zc & 1;
    int b = (zc >> 1) & (BATCH - 1);
    int which = zc >> 2;
    const float* src = which ? src2 : src1;
    float* dst = which ? g_p2T : g_p1T;
    int n0 = blockIdx.x * 32;
    int c0 = ct * 32;
    int lx = threadIdx.x & 31, ly = threadIdx.x >> 5;
    #pragma unroll
    for (int r = 0; r < 4; r++) {
        int c = c0 + ly + r * 8;
        t[ly + r * 8][lx] = src[((size_t)b * DD + c) * N1 + n0 + lx];
    }
    __syncthreads();
    #pragma unroll
    for (int r = 0; r < 4; r++) {
        int n = n0 + ly + r * 8;
        dst[((size_t)b * N1 + n) * DD + c0 + lx] = t[lx][ly + r * 8];
    }
}

// ---------------- fused: norms A/B + comb features (split) + comb norm ----------------
__global__ void k_normsComb()
{
    int t = blockIdx.x * blockDim.x + threadIdx.x;
    if (t >= BATCH * 4096) return;
    int b = t / 4096, n = t % 4096;
    float wf = g_wf[t], wr = g_wr[t];
    float v0 = g_vw[t * 3 + 0], v1 = g_vw[t * 3 + 1], v2 = g_vw[t * 3 + 2];
    float sA = 0.f, sB = 0.f;
    #pragma unroll 8
    for (int c = 0; c < CP; c++) {
        float a = g_F1[(b * CP + c) * 4096 + n];
        float bb = g_F2[(b * CP + c) * 4096 + n];
        sA += a * a;
        sB += bb * bb;
        float cv = 0.f;
        if (c < 67) cv = wf * a;
        else if (c == 67) cv = wr * v0;
        else if (c == 68) cv = wr * v1;
        else if (c == 69) cv = wr * v2;
        g_CBs[(b * CP + c) * 4096 + n] = tf32split(cv);
    }
    g_nA[t] = sA;
    g_nB[t] = sB;
    g_nC[t] = wf * wf * sA + wr * wr * (v0 * v0 + v1 * v1 + v2 * v2);
}

// ---------------- distance GEMM on tensor cores (3xTF32, pre-split, 4m x 2n warps) ----------------
#define CPK 40
#define S2 132
#define SLAB2 (CPK * S2)
#define DIST_SMEM ((2 * SLAB2 * 2 + 256) * 4)

__global__ void __launch_bounds__(256) k_dist_tc(int sel)
{
    extern __shared__ float2 dsm2[];
    float2* As2 = dsm2;                 // [CPK][S2] (hi,lo)
    float2* Bs2 = As2 + SLAB2;
    float* nAs = (float*)(Bs2 + SLAB2); // 128
    float* nBs = nAs + 128;             // 128

    const float2* FAs = sel ? g_CBs : g_F1s;
    const float2* FBs = sel ? g_CBs : g_F2s;
    const float* nAv = sel ? g_nC : g_nA;
    const float* nBv = sel ? g_nC : g_nB;

    int b = blockIdx.z;
    int i0 = blockIdx.y * 128, j0 = blockIdx.x * 128;
    const float2* Asrc = FAs + (size_t)b * CP * N1 + i0;
    const float2* Bsrc = FBs + (size_t)b * CP * N2 + j0;

    int tid = threadIdx.x;
    if (tid < 128) {
        nAs[tid] = nAv[b * N1 + i0 + tid];
        nBs[tid] = nBv[b * N2 + j0 + tid];
    }

    int warp = tid >> 5, lane = tid & 31;
    int gid = lane >> 2, tig = lane & 3;
    int wm2 = warp & 3;        // m quadrant: 32 rows
    int wn2 = warp >> 2;       // n half: 64 cols
    int mi0 = wm2 * 32 + gid;
    int nb0 = wn2 * 64 + gid;

    float acc[2][8][4];
    #pragma unroll
    for (int mt = 0; mt < 2; mt++)
        #pragma unroll
        for (int nt = 0; nt < 8; nt++)
            #pragma unroll
            for (int u = 0; u < 4; u++) acc[mt][nt][u] = 0.f;

    for (int kb = 0; kb < CP; kb += CPK) {
        // stage chunk: pure copy (float4 = 2 float2), 64 float4 per row
        for (int idx = tid; idx < CPK * 64 * 2; idx += 256) {
            int which = idx >= CPK * 64;
            int r = which ? idx - CPK * 64 : idx;
            int k = r >> 6, c2 = (r & 63) << 1;   // float2 col pair
            const float2* src = which ? Bsrc : Asrc;
            float2* dst = (which ? Bs2 : As2) + k * S2 + c2;
            *(float4*)dst = *(const float4*)(src + (size_t)(kb + k) * 4096 + c2);
        }
        __syncthreads();

        #pragma unroll
        for (int kk = 0; kk < CPK; kk += 8) {
            const float2* r0 = As2 + (kk + tig) * S2;
            const float2* r1 = As2 + (kk + tig + 4) * S2;
            float2 a00 = r0[mi0],      a01 = r0[mi0 + 8];
            float2 a02 = r1[mi0],      a03 = r1[mi0 + 8];
            float2 a10 = r0[mi0 + 16], a11 = r0[mi0 + 24];
            float2 a12 = r1[mi0 + 16], a13 = r1[mi0 + 24];
            const float2* q0 = Bs2 + (kk + tig) * S2;
            const float2* q1 = Bs2 + (kk + tig + 4) * S2;
            #pragma unroll
            for (int nt = 0; nt < 8; nt++) {
                int nb = nb0 + nt * 8;
                float2 b0 = q0[nb], b1 = q1[nb];
                MMA_TF32(acc[0][nt], a00.y, a01.y, a02.y, a03.y, b0.x, b1.x);  // lo*hi
                MMA_TF32(acc[0][nt], a00.x, a01.x, a02.x, a03.x, b0.y, b1.y);  // hi*lo
                MMA_TF32(acc[0][nt], a00.x, a01.x, a02.x, a03.x, b0.x, b1.x);  // hi*hi
                MMA_TF32(acc[1][nt], a10.y, a11.y, a12.y, a13.y, b0.x, b1.x);
                MMA_TF32(acc[1][nt], a10.x, a11.x, a12.x, a13.x, b0.y, b1.y);
                MMA_TF32(acc[1][nt], a10.x, a11.x, a12.x, a13.x, b0.x, b1.x);
            }
        }
        __syncthreads();
    }

    float* drow = g_dist + (size_t)b * N1 * N2;
    #pragma unroll
    for (int mt = 0; mt < 2; mt++) {
        int mrow = wm2 * 32 + mt * 16 + gid;
        float ni0 = nAs[mrow], ni1 = nAs[mrow + 8];
        size_t ro0 = (size_t)(i0 + mrow) * N2 + j0;
        size_t ro1 = ro0 + (size_t)8 * N2;
        #pragma unroll
        for (int nt = 0; nt < 8; nt++) {
            int jc = wn2 * 64 + nt * 8 + tig * 2;
            float nj0 = nBs[jc], nj1 = nBs[jc + 1];
            float2 o0, o1;
            o0.x = fmaxf(ni0 - 2.f * acc[mt][nt][0] + nj0, 0.f);
            o0.y = fmaxf(ni0 - 2.f * acc[mt][nt][1] + nj1, 0.f);
            o1.x = fmaxf(ni1 - 2.f * acc[mt][nt][2] + nj0, 0.f);
            o1.y = fmaxf(ni1 - 2.f * acc[mt][nt][3] + nj1, 0.f);
            *(float2*)(drow + ro0 + jc) = o0;
            *(float2*)(drow + ro1 + jc) = o1;
        }
    }
}

// ---------------- top-K v5: 4 rows/block, 4 concurrent extraction warps ----------------
#define RPB 4
__global__ void __launch_bounds__(256) k_topk(int sel)
{
    __shared__ unsigned long long segmin[RPB][256];   // 8 KB
    int q0 = blockIdx.x * RPB;
    int* idxo = sel ? g_idx2 : g_idx1;
    int tid = threadIdx.x;

    #pragma unroll
    for (int rr = 0; rr < RPB; rr++) {
        const float* row = g_dist + (size_t)(q0 + rr) * N2;
        int basej = tid * 16;
        float mv = __int_as_float(0x7f7fffff);
        int mj = basej;
        #pragma unroll
        for (int i = 0; i < 4; i++) {
            float4 f = *(const float4*)(row + basej + i * 4);
            int j0 = basej + i * 4;
            if (f.x < mv) { mv = f.x; mj = j0 + 0; }
            if (f.y < mv) { mv = f.y; mj = j0 + 1; }
            if (f.z < mv) { mv = f.z; mj = j0 + 2; }
            if (f.w < mv) { mv = f.w; mj = j0 + 3; }
        }
        segmin[rr][tid] = ((unsigned long long)__float_as_uint(mv) << 32) | (unsigned)mj;
    }
    __syncthreads();

    int w = tid >> 5, lane = tid & 31;
    if (w < RPB) {
        int q = q0 + w;
        const float* row = g_dist + (size_t)q * N2;
        unsigned long long r[8];
        #pragma unroll
        for (int i = 0; i < 8; i++) r[i] = segmin[w][lane + 32 * i];
        int ex[KN];
        #pragma unroll
        for (int i = 0; i < KN; i++) ex[i] = -1;

        for (int k = 0; k < KN; k++) {
            unsigned long long m = r[0];
            #pragma unroll
            for (int i = 1; i < 8; i++) m = u64min(m, r[i]);
            #pragma unroll
            for (int o = 16; o; o >>= 1)
                m = u64min(m, __shfl_xor_sync(0xffffffffu, m, o));
            int j = (int)(unsigned)(m & 0xffffffffULL);
            #pragma unroll
            for (int i = 0; i < KN; i++) if (i == k) ex[i] = j;
            if (lane == 0) idxo[q * KN + k] = j;
            if (k == KN - 1) break;

            int seg = j >> 4;
            unsigned long long v = ~0ull;
            if (lane < 16) {
                int idx = seg * 16 + lane;
                float f = __ldg(row + idx);
                v = ((unsigned long long)__float_as_uint(f) << 32) | (unsigned)idx;
                #pragma unroll
                for (int i = 0; i < KN; i++)
                    if (i <= k && ex[i] == idx) v = ~0ull;
            }
            #pragma unroll
            for (int o = 8; o; o >>= 1)
                v = u64min(v, __shfl_xor_sync(0xffffffffu, v, o));
            unsigned long long vb = __shfl_sync(0xffffffffu, v, 0);
            int slot = seg >> 5, ln = seg & 31;
            #pragma unroll
            for (int i = 0; i < 8; i++)
                if (i == slot && lane == ln) r[i] = vb;
        }
    }
}

// ---------------- fused MLP on tensor cores (bf16 3-term split, m16n8k16) ----------------
#define TNP 8
#define SY 132
#define MX   0
#define MYO  (144 * SY)
#define MWC  (MYO + 128 * SY)
#define MB   (MWC + 24 * SY * 2)
#define MH2  (MB + 384)
#define MSW2 (MH2 + 1024)
#define MSB2 (MSW2 + 1024)
#define MIDX (MSB2 + 128)
#define MLP2_SMEM ((MIDX + 128) * 4)

__global__ void __launch_bounds__(512) k_mlp_tc(
    const float* __restrict__ b0g, const float* __restrict__ b1g,
    const float* __restrict__ b2g,
    const float* __restrict__ n1w0, const float* __restrict__ n1b0,
    const float* __restrict__ n1w1, const float* __restrict__ n1b1,
    const float* __restrict__ n1w2, const float* __restrict__ n1b2)
{
    extern __shared__ float sm[];
    float* Xbuf = sm + MX;
    float* Ybuf = sm + MYO;
    uint2* Wc = (uint2*)(sm + MWC);
    float* biasS = sm + MB;
    float* h2s = sm + MH2;
    float* sw2 = sm + MSW2;
    float* sb2 = sm + MSB2;
    int* idxs = (int*)(sm + MIDX);

    int tid = threadIdx.x;
    int warp = tid >> 5, lane = tid & 31;
    int gid = lane >> 2, tig = lane & 3;
    int wm = warp & 7, nh = warp >> 3;
    int mi = wm * 16 + gid;
    int base = blockIdx.x * TNP;

    if (tid < 128) {
        idxs[tid] = g_idx1[base * KN + tid];
        #pragma unroll
        for (int r = 0; r < 8; r++) sw2[tid + 128 * r] = n1w2[tid + 128 * r];
        sb2[tid] = n1b2[tid];
        biasS[tid] = b0g[tid];
        biasS[128 + tid] = b1g[tid];
        biasS[256 + tid] = b2g[tid];
    }
    __syncthreads();

    for (int e = tid; e < 144 * 128; e += 512) {
        int i = e >> 7, col = e & 127;
        int tn = col >> 4;
        int pt = base + tn;
        int b = pt >> 12;
        int j = idxs[col];
        float v;
        if (i < 64) v = g_p1T[(size_t)pt * DD + i];
        else if (i < 128) v = g_p2T[((size_t)b * N2 + j) * DD + (i - 64)];
        else if (i < 131) v = g_x2T[(b * N2 + j) * 3 + (i - 128)] - g_x1T[pt * 3 + (i - 128)];
        else v = 0.f;
        Xbuf[i * SY + col] = v;
    }
    __syncthreads();

    if (tid < 128) {
        int col = tid;
        float dx0 = Xbuf[128 * SY + col];
        float dx1 = Xbuf[129 * SY + col];
        float dx2 = Xbuf[130 * SY + col];
        float h[8];
        #pragma unroll
        for (int j = 0; j < 8; j++) {
            float s = n1w0[j * 3 + 0] * dx0 + n1w0[j * 3 + 1] * dx1 + n1w0[j * 3 + 2] * dx2 + n1b0[j];
            h[j] = fmaxf(s, 0.f);
        }
        #pragma unroll
        for (int j = 0; j < 8; j++) {
            float s = n1b1[j];
            #pragma unroll
            for (int m = 0; m < 8; m++) s += n1w1[j * 8 + m] * h[m];
            h2s[col * 8 + j] = fmaxf(s, 0.f);
        }
    }

    #pragma unroll 1
    for (int l = 0; l < 3; l++) {
        const int KPL = (l == 0) ? 72 : 64;
        const float* Xin = (l == 1) ? Ybuf : Xbuf;
        float* Yout = (l == 1) ? Xbuf : Ybuf;

        float acc[8][4];
        #pragma unroll
        for (int nti = 0; nti < 8; nti++) {
            int c0 = (nh * 8 + nti) * 8 + tig * 2;
            acc[nti][0] = biasS[l * 128 + c0];
            acc[nti][1] = biasS[l * 128 + c0 + 1];
            acc[nti][2] = acc[nti][0];
            acc[nti][3] = acc[nti][1];
        }

        for (int kbp = 0; kbp < KPL; kbp += 24) {
            int cs = (KPL - kbp < 24) ? (KPL - kbp) : 24;
            __syncthreads();
            for (int e = tid; e < cs * 128; e += 512) {
                int kl = e >> 7, c = e & 127;
                Wc[kl * SY + c] = g_wbf[l][kbp + kl][c];
            }
            __syncthreads();
            for (int pp = 0; pp < cs; pp += 8) {
                int kp0 = kbp + pp + tig;
                int kp1 = kp0 + 4;
                int r00 = 2 * kp0, r10 = 2 * kp1;
                float x00 = Xin[r00 * SY + mi];
                float x01 = Xin[(r00 + 1) * SY + mi];
                float x02 = Xin[r00 * SY + mi + 8];
                float x03 = Xin[(r00 + 1) * SY + mi + 8];
                float x10 = Xin[r10 * SY + mi];
                float x11 = Xin[(r10 + 1) * SY + mi];
                float x12 = Xin[r10 * SY + mi + 8];
                float x13 = Xin[(r10 + 1) * SY + mi + 8];
                float h00 = bf16_trunc(x00), h01 = bf16_trunc(x01);
                float h02 = bf16_trunc(x02), h03 = bf16_trunc(x03);
                float h10 = bf16_trunc(x10), h11 = bf16_trunc(x11);
                float h12 = bf16_trunc(x12), h13 = bf16_trunc(x13);
                unsigned a0h = packbf2(h00, h01), a1h = packbf2(h02, h03);
                unsigned a2h = packbf2(h10, h11), a3h = packbf2(h12, h13);
                unsigned a0l = packbf2(x00 - h00, x01 - h01);
                unsigned a1l = packbf2(x02 - h02, x03 - h03);
                unsigned a2l = packbf2(x10 - h10, x11 - h11);
                unsigned a3l = packbf2(x12 - h12, x13 - h13);
                const uint2* w0p = Wc + (pp + tig) * SY;
                const uint2* w1p = Wc + (pp + tig + 4) * SY;
                #pragma unroll
                for (int nti = 0; nti < 8; nti++) {
                    int nb = (nh * 8 + nti) * 8 + gid;
                    uint2 b0 = w0p[nb], b1 = w1p[nb];
                    MMA_BF16(acc[nti], a0l, a1l, a2l, a3l, b0.x, b1.x);
                    MMA_BF16(acc[nti], a0h, a1h, a2h, a3h, b0.y, b1.y);
                    MMA_BF16(acc[nti], a0h, a1h, a2h, a3h, b0.x, b1.x);
                }
            }
        }
        __syncthreads();
        #pragma unroll
        for (int nti = 0; nti < 8; nti++) {
            int c0 = (nh * 8 + nti) * 8 + tig * 2;
            Yout[c0 * SY + mi] = leakyf(acc[nti][0]);
            Yout[(c0 + 1) * SY + mi] = leakyf(acc[nti][1]);
            Yout[c0 * SY + mi + 8] = leakyf(acc[nti][2]);
            Yout[(c0 + 1) * SY + mi + 8] = leakyf(acc[nti][3]);
        }
    }
    __syncthreads();

    {
        int col = tid >> 2, cq = tid & 3;
        float hj[8];
        #pragma unroll
        for (int j = 0; j < 8; j++) hj[j] = h2s[col * 8 + j];
        #pragma unroll 4
        for (int cc = 0; cc < 32; cc++) {
            int c = cq * 32 + cc;
            float s = sb2[c];
            #pragma unroll
            for (int j = 0; j < 8; j++) s += sw2[c * 8 + j] * hj[j];
            Xbuf[col * SY + c] = fmaxf(s, 0.f);
        }
    }
    __syncthreads();

    for (int e = tid; e < 1024; e += 512) {
        int pt = e >> 7, c = e & 127;
        const float* yr = Ybuf + c * SY + pt * 16;
        const float* sc = Xbuf + (pt * 16) * SY + c;
        float a = 0.f;
        #pragma unroll
        for (int k = 0; k < 16; k++) a += sc[k * SY] * yr[k];
        g_p2p[(size_t)(base + pt) * CO + c] = a;
    }
}

// ---------------- patch aggregation ----------------
__global__ void __launch_bounds__(128) k_patch(
    const float* __restrict__ n2w0, const float* __restrict__ n2b0,
    const float* __restrict__ n2w1, const float* __restrict__ n2b1,
    const float* __restrict__ n2w2, const float* __restrict__ n2b2,
    float* __restrict__ out)
{
    __shared__ float h2s[16][8];
    __shared__ int js[16];
    int q = blockIdx.x;
    int b = q / N1, n = q % N1;
    int tid = threadIdx.x;
    if (tid < 16) {
        int j = g_idx2[q * KN + tid];
        js[tid] = j;
        float dx0 = g_x1T[(b * N1 + j) * 3 + 0] - g_x1T[q * 3 + 0];
        float dx1 = g_x1T[(b * N1 + j) * 3 + 1] - g_x1T[q * 3 + 1];
        float dx2 = g_x1T[(b * N1 + j) * 3 + 2] - g_x1T[q * 3 + 2];
        float h[8];
        #pragma unroll
        for (int jj = 0; jj < 8; jj++) {
            float s = n2w0[jj * 3 + 0] * dx0 + n2w0[jj * 3 + 1] * dx1 + n2w0[jj * 3 + 2] * dx2 + n2b0[jj];
            h[jj] = fmaxf(s, 0.f);
        }
        #pragma unroll
        for (int jj = 0; jj < 8; jj++) {
            float s = n2b1[jj];
            #pragma unroll
            for (int m = 0; m < 8; m++) s += n2w1[jj * 8 + m] * h[m];
            h2s[tid][jj] = fmaxf(s, 0.f);
        }
    }
    __syncthreads();
    int c = tid;
    float w2r[8];
    #pragma unroll
    for (int j = 0; j < 8; j++) w2r[j] = n2w2[c * 8 + j];
    float bc = n2b2[c];
    float acc = 0.f;
    #pragma unroll
    for (int k = 0; k < KN; k++) {
        float s = bc;
        #pragma unroll
        for (int j = 0; j < 8; j++) s += w2r[j] * h2s[k][j];
        s = fmaxf(s, 0.f);
        acc += s * g_p2p[((size_t)b * N1 + js[k]) * CO + c];
    }
    out[(size_t)b * CO * N1 + (size_t)c * N1 + n] = acc;
}

// ---------------- launch ----------------
extern "C" void kernel_launch(void* const* d_in, const int* in_sizes, int n_in,
                              void* d_out, int out_size)
{
    int s = (n_in >= 31) ? 0 : -2;
    const float* xyz1 = (const float*)d_in[0];
    const float* xyz2 = (const float*)d_in[1];
    const float* pts1 = (const float*)d_in[2];
    const float* pts2 = (const float*)d_in[3];
    const float* vel1 = (const float*)d_in[4];
    const float* fcc  = (const float*)d_in[8 + s];
    const float* fcv  = (const float*)d_in[9 + s];
    const float* wxyz = (const float*)d_in[10 + s];
    const float* wpts = (const float*)d_in[12 + s];
    const float* mw0 = (const float*)d_in[13 + s];
    const float* mb0 = (const float*)d_in[14 + s];
    const float* mw1 = (const float*)d_in[15 + s];
    const float* mb1 = (const float*)d_in[16 + s];
    const float* mw2 = (const float*)d_in[17 + s];
    const float* mb2 = (const float*)d_in[18 + s];
    const float* n1w0 = (const float*)d_in[19 + s];
    const float* n1b0 = (const float*)d_in[20 + s];
    const float* n2w0 = (const float*)d_in[21 + s];
    const float* n2b0 = (const float*)d_in[22 + s];
    const float* n1w1 = (const float*)d_in[23 + s];
    const float* n1b1 = (const float*)d_in[24 + s];
    const float* n2w1 = (const float*)d_in[25 + s];
    const float* n2b1 = (const float*)d_in[26 + s];
    const float* n1w2 = (const float*)d_in[27 + s];
    const float* n1b2 = (const float*)d_in[28 + s];
    const float* n2w2 = (const float*)d_in[29 + s];
    const float* n2b2 = (const float*)d_in[30 + s];

    float* out = (float*)d_out;
    const int patch_elems = BATCH * CO * N1;
    const int vw_elems = BATCH * N1 * 3;
    float* out_vw = (out_size >= patch_elems + vw_elems) ? (out + patch_elems) : nullptr;

    cudaFuncSetAttribute(k_mlp_tc, cudaFuncAttributeMaxDynamicSharedMemorySize, (int)MLP2_SMEM);
    cudaFuncSetAttribute(k_dist_tc, cudaFuncAttributeMaxDynamicSharedMemorySize, (int)DIST_SMEM);

    const int prep_total = 2 * BATCH * CP * N1 + 2 * BATCH * 3 * N1;
    dim3 gg(N2 / 128, N1 / 128, BATCH);
    dim3 gt(N1 / 32, 2 * BATCH * 2);

    k_rigid<<<(BATCH * N1 + 127) / 128, 128>>>(xyz1, vel1, fcc, fcv, out_vw);
    k_prep<<<(prep_total + 255) / 256, 256>>>(xyz1, xyz2, pts1, pts2, wxyz, wpts);
    k_normsComb<<<(BATCH * 4096 + 127) / 128, 128>>>();
    k_dist_tc<<<gg, 256, DIST_SMEM>>>(0);
    k_topk<<<BATCH * N1 / RPB, 256>>>(0);
    k_transp<<<gt, 256>>>(pts1, pts2);
    k_wprep<<<108, 256>>>(mw0, mw1, mw2);
    k_mlp_tc<<<(BATCH * N1) / TNP, 512, MLP2_SMEM>>>(mb0, mb1, mb2,
                                                     n1w0, n1b0, n1w1, n1b1, n1w2, n1b2);
    k_dist_tc<<<gg, 256, DIST_SMEM>>>(1);
    k_topk<<<BATCH * N1 / RPB, 256>>>(1);
    k_patch<<<BATCH * N1, 128>>>(n2w0, n2b0, n2w1, n2b1, n2w2, n2b2, out);
}

// round 15
// speedup vs baseline: 1.1626x; 1.0587x over previous
#include <cuda_runtime.h>
#include <cuda_bf16.h>
#include <math.h>

#define BATCH 2
#define N1 4096
#define N2 4096
#define DD 64
#define KN 16
#define KCC 8
#define CP 80      // padded feature channels (67 / 70 used)
#define CO 128

// ---------------- scratch (static device memory; no runtime alloc) ----------------
__device__ float g_dist[(size_t)BATCH * N1 * N2];        // 134 MB
__device__ float g_F1[BATCH * CP * N1];
__device__ float g_F2[BATCH * CP * N2];
__device__ float2 g_F1s[BATCH * CP * N1];   // tf32 hi/lo split
__device__ float2 g_F2s[BATCH * CP * N2];
__device__ float2 g_CBs[BATCH * CP * N1];
__device__ float g_nA[BATCH * N1];
__device__ float g_nB[BATCH * N2];
__device__ float g_nC[BATCH * N1];
__device__ int   g_idx1[BATCH * N1 * KN];
__device__ int   g_idx2[BATCH * N1 * KN];
__device__ float g_vw[BATCH * N1 * 3];
__device__ float g_wf[BATCH * N1];
__device__ float g_wr[BATCH * N1];
__device__ float g_p1T[BATCH * N1 * DD];
__device__ float g_p2T[BATCH * N2 * DD];
__device__ float g_x1T[BATCH * N1 * 3];
__device__ float g_x2T[BATCH * N2 * 3];
__device__ float g_p2p[(size_t)BATCH * N1 * CO];
__device__ uint2 g_wbf[3][72][128];     // bf16 hi/lo split, transposed MLP weights (k-pairs)

__device__ __forceinline__ float leakyf(float x) { return x >= 0.f ? x : 0.1f * x; }
__device__ __forceinline__ unsigned long long u64min(unsigned long long a, unsigned long long b) {
    return a < b ? a : b;
}

// ---- tf32 helpers (dist kernel) ----
__device__ __forceinline__ float f2tf32f(float x) {
    unsigned int r;
    asm("cvt.rna.tf32.f32 %0, %1;" : "=r"(r) : "f"(x));
    return __uint_as_float(r);
}
__device__ __forceinline__ float2 tf32split(float v) {
    float h = f2tf32f(v);
    return make_float2(h, f2tf32f(v - h));
}

#define MMA_TF32(acc, A0, A1, A2, A3, B0, B1)                                   \
    asm volatile("mma.sync.aligned.m16n8k8.row.col.f32.tf32.tf32.f32 "          \
                 "{%0,%1,%2,%3}, {%4,%5,%6,%7}, {%8,%9}, {%0,%1,%2,%3};"        \
                 : "+f"(acc[0]), "+f"(acc[1]), "+f"(acc[2]), "+f"(acc[3])       \
                 : "r"(__float_as_uint(A0)), "r"(__float_as_uint(A1)),          \
                   "r"(__float_as_uint(A2)), "r"(__float_as_uint(A3)),          \
                   "r"(__float_as_uint(B0)), "r"(__float_as_uint(B1)))

// ---- bf16 helpers (mlp kernel) ----
__device__ __forceinline__ float bf16_trunc(float x) {
    return __uint_as_float(__float_as_uint(x) & 0xffff0000u);
}
__device__ __forceinline__ unsigned packbf2(float lo_elem, float hi_elem) {
    __nv_bfloat162 v = __floats2bfloat162_rn(lo_elem, hi_elem);
    return *(unsigned*)&v;
}

#define MMA_BF16(acc, A0, A1, A2, A3, B0, B1)                                   \
    asm volatile("mma.sync.aligned.m16n8k16.row.col.f32.bf16.bf16.f32 "         \
                 "{%0,%1,%2,%3}, {%4,%5,%6,%7}, {%8,%9}, {%0,%1,%2,%3};"        \
                 : "+f"(acc[0]), "+f"(acc[1]), "+f"(acc[2]), "+f"(acc[3])       \
                 : "r"(A0), "r"(A1), "r"(A2), "r"(A3), "r"(B0), "r"(B1))

// ---------------- rigid 3x3 least squares + mask ----------------
__global__ void k_rigid(const float* __restrict__ xyz1, const float* __restrict__ vel1,
                        const float* __restrict__ fcc, const float* __restrict__ fcv,
                        float* __restrict__ out_vw)
{
    int t = blockIdx.x * blockDim.x + threadIdx.x;
    if (t >= BATCH * N1) return;
    int b = t / N1, n = t % N1;
    const float* cc = fcc + (size_t)t * KCC * 3;
    const float* cv = fcv + (size_t)t * KCC;
    double A00 = 1e-6, A01 = 0, A02 = 0, A11 = 1e-6, A12 = 0, A22 = 1e-6;
    double r0 = 0, r1 = 0, r2 = 0;
    for (int k = 0; k < KCC; k++) {
        double x = cc[k * 3 + 0], y = cc[k * 3 + 1], z = cc[k * 3 + 2];
        double inv = 1.0 / sqrt(x * x + y * y + z * z);
        x *= inv; y *= inv; z *= inv;
        A00 += x * x; A01 += x * y; A02 += x * z;
        A11 += y * y; A12 += y * z; A22 += z * z;
        double v = (double)cv[k];
        r0 += x * v; r1 += y * v; r2 += z * v;
    }
    double c00 = A11 * A22 - A12 * A12;
    double c01 = A01 * A22 - A12 * A02;
    double c02 = A01 * A12 - A11 * A02;
    double det = A00 * c00 - A01 * c01 + A02 * c02;
    double id = 1.0 / det;
    double v0 = (r0 * c00 - A01 * (r1 * A22 - A12 * r2) + A02 * (r1 * A12 - A11 * r2)) * id;
    double v1 = (A00 * (r1 * A22 - A12 * r2) - r0 * c01 + A02 * (A01 * r2 - r1 * A02)) * id;
    double v2 = (A00 * (A11 * r2 - r1 * A12) - A01 * (A01 * r2 - r1 * A02) + r0 * c02) * id;

    float fx = xyz1[(b * 3 + 0) * N1 + n];
    float fy = xyz1[(b * 3 + 1) * N1 + n];
    float fz = xyz1[(b * 3 + 2) * N1 + n];
    double inl = 1.0 / sqrt((double)fx * fx + (double)fy * fy + (double)fz * fz);
    double err = fabs((v0 * fx + v1 * fy + v2 * fz) * inl - (double)vel1[t]);
    bool m = (err <= 5.0);
    g_wf[t] = m ? 0.1f : 0.9f;
    g_wr[t] = m ? 0.9f : 0.1f;
    g_vw[t * 3 + 0] = (float)v0;
    g_vw[t * 3 + 1] = (float)v1;
    g_vw[t * 3 + 2] = (float)v2;
    if (out_vw) {
        out_vw[t * 3 + 0] = (float)v0;
        out_vw[t * 3 + 1] = (float)v1;
        out_vw[t * 3 + 2] = (float)v2;
    }
}

// ---------------- fused: weighted feature build (fp32 + tf32 split) + xyz transposes ----------------
__global__ void k_prep(const float* __restrict__ xyz1, const float* __restrict__ xyz2,
                       const float* __restrict__ pts1, const float* __restrict__ pts2,
                       const float* __restrict__ wxyz_p, const float* __restrict__ wpts_p)
{
    float wx = *wxyz_p, wp = *wpts_p;
    const int totalF = BATCH * CP * N1;
    const int tx3 = BATCH * 3 * N1;
    const int total = 2 * totalF + 2 * tx3;
    for (int e = blockIdx.x * blockDim.x + threadIdx.x; e < total;
         e += gridDim.x * blockDim.x) {
        if (e < 2 * totalF) {
            int which = e / totalF;
            int r = e % totalF;
            int b = r / (CP * N1);
            int c = (r / N1) % CP;
            int n = r % N1;
            const float* xyz = which ? xyz2 : xyz1;
            const float* pts = which ? pts2 : pts1;
            float v = 0.f;
            if (c < 3) v = wx * xyz[(b * 3 + c) * N1 + n];
            else if (c < 67) v = wp * pts[(b * DD + (c - 3)) * N1 + n];
            if (which) { g_F2[r] = v; g_F2s[r] = tf32split(v); }
            else       { g_F1[r] = v; g_F1s[r] = tf32split(v); }
        } else {
            int r = e - 2 * totalF;
            if (r < tx3) {
                int b = r / (3 * N1), c = (r / N1) % 3, n = r % N1;
                g_x1T[(b * N1 + n) * 3 + c] = xyz1[r];
            } else {
                r -= tx3;
                int b = r / (3 * N1), c = (r / N1) % 3, n = r % N1;
                g_x2T[(b * N2 + n) * 3 + c] = xyz2[r];
            }
        }
    }
}

// ---------------- MLP weight transpose + bf16 hi/lo split (runs once) ----------------
__global__ void k_wprep(const float* __restrict__ w0, const float* __restrict__ w1,
                        const float* __restrict__ w2)
{
    const int per = 72 * 128;
    for (int e = blockIdx.x * blockDim.x + threadIdx.x; e < 3 * per;
         e += gridDim.x * blockDim.x) {
        int l = e / per;
        int r = e % per;
        int kp = r >> 7, c = r & 127;
        int KD = (l == 0) ? 131 : 128;
        const float* w = (l == 0) ? w0 : (l == 1) ? w1 : w2;
        int k0 = 2 * kp, k1 = 2 * kp + 1;
        float v0 = (k0 < KD) ? w[c * KD + k0] : 0.f;
        float v1 = (k1 < KD) ? w[c * KD + k1] : 0.f;
        float h0 = bf16_trunc(v0), h1 = bf16_trunc(v1);
        uint2 o;
        o.x = packbf2(h0, h1);
        o.y = packbf2(v0 - h0, v1 - h1);
        g_wbf[l][kp][c] = o;
    }
}

// ---------------- coalesced tiled transpose: [B][C][N] -> [B][N][C], C=64 ----------------
__global__ void __launch_bounds__(256) k_transp(const float* __restrict__ src1,
                                                const float* __restrict__ src2)
{
    __shared__ float t[32][33];
    int zc = blockIdx.y;
    int ct = zc & 1;
    int b = (zc >> 1) & (BATCH - 1);
    int which = zc >> 2;
    const float* src = which ? src2 : src1;
    float* dst = which ? g_p2T : g_p1T;
    int n0 = blockIdx.x * 32;
    int c0 = ct * 32;
    int lx = threadIdx.x & 31, ly = threadIdx.x >> 5;
    #pragma unroll
    for (int r = 0; r < 4; r++) {
        int c = c0 + ly + r * 8;
        t[ly + r * 8][lx] = src[((size_t)b * DD + c) * N1 + n0 + lx];
    }
    __syncthreads();
    #pragma unroll
    for (int r = 0; r < 4; r++) {
        int n = n0 + ly + r * 8;
        dst[((size_t)b * N1 + n) * DD + c0 + lx] = t[lx][ly + r * 8];
    }
}

// ---------------- fused: norms A/B + comb features (split) + comb norm ----------------
__global__ void k_normsComb()
{
    int t = blockIdx.x * blockDim.x + threadIdx.x;
    if (t >= BATCH * 4096) return;
    int b = t / 4096, n = t % 4096;
    float wf = g_wf[t], wr = g_wr[t];
    float v0 = g_vw[t * 3 + 0], v1 = g_vw[t * 3 + 1], v2 = g_vw[t * 3 + 2];
    float sA = 0.f, sB = 0.f;
    #pragma unroll 8
    for (int c = 0; c < CP; c++) {
        float a = g_F1[(b * CP + c) * 4096 + n];
        float bb = g_F2[(b * CP + c) * 4096 + n];
        sA += a * a;
        sB += bb * bb;
        float cv = 0.f;
        if (c < 67) cv = wf * a;
        else if (c == 67) cv = wr * v0;
        else if (c == 68) cv = wr * v1;
        else if (c == 69) cv = wr * v2;
        g_CBs[(b * CP + c) * 4096 + n] = tf32split(cv);
    }
    g_nA[t] = sA;
    g_nB[t] = sB;
    g_nC[t] = wf * wf * sA + wr * wr * (v0 * v0 + v1 * v1 + v2 * v2);
}

// ---------------- distance GEMM on tensor cores (3xTF32, pre-split, 4m x 2n warps) ----------------
// sel==1 (self-distance) is symmetric: only upper-triangle blocks computed;
// off-diagonal blocks also write the transposed tile via an smem round-trip.
#define CPK 40
#define S2 132
#define SLAB2 (CPK * S2)
#define DIST_SMEM ((2 * SLAB2 * 2 + 256) * 4)
#define TS 129   // transpose tile stride (odd -> low-conflict column reads)

__global__ void __launch_bounds__(256) k_dist_tc(int sel)
{
    extern __shared__ float2 dsm2[];
    float2* As2 = dsm2;                 // [CPK][S2] (hi,lo)
    float2* Bs2 = As2 + SLAB2;
    float* nAs = (float*)(Bs2 + SLAB2); // 128
    float* nBs = nAs + 128;             // 128

    int bx = blockIdx.x, by = blockIdx.y;
    if (sel && by > bx) return;         // symmetry: skip lower triangle

    const float2* FAs = sel ? g_CBs : g_F1s;
    const float2* FBs = sel ? g_CBs : g_F2s;
    const float* nAv = sel ? g_nC : g_nA;
    const float* nBv = sel ? g_nC : g_nB;

    int b = blockIdx.z;
    int i0 = by * 128, j0 = bx * 128;
    const float2* Asrc = FAs + (size_t)b * CP * N1 + i0;
    const float2* Bsrc = FBs + (size_t)b * CP * N2 + j0;

    int tid = threadIdx.x;
    if (tid < 128) {
        nAs[tid] = nAv[b * N1 + i0 + tid];
        nBs[tid] = nBv[b * N2 + j0 + tid];
    }

    int warp = tid >> 5, lane = tid & 31;
    int gid = lane >> 2, tig = lane & 3;
    int wm2 = warp & 3;        // m quadrant: 32 rows
    int wn2 = warp >> 2;       // n half: 64 cols
    int mi0 = wm2 * 32 + gid;
    int nb0 = wn2 * 64 + gid;

    float acc[2][8][4];
    #pragma unroll
    for (int mt = 0; mt < 2; mt++)
        #pragma unroll
        for (int nt = 0; nt < 8; nt++)
            #pragma unroll
            for (int u = 0; u < 4; u++) acc[mt][nt][u] = 0.f;

    for (int kb = 0; kb < CP; kb += CPK) {
        for (int idx = tid; idx < CPK * 64 * 2; idx += 256) {
            int which = idx >= CPK * 64;
            int r = which ? idx - CPK * 64 : idx;
            int k = r >> 6, c2 = (r & 63) << 1;
            const float2* src = which ? Bsrc : Asrc;
            float2* dst = (which ? Bs2 : As2) + k * S2 + c2;
            *(float4*)dst = *(const float4*)(src + (size_t)(kb + k) * 4096 + c2);
        }
        __syncthreads();

        #pragma unroll
        for (int kk = 0; kk < CPK; kk += 8) {
            const float2* r0 = As2 + (kk + tig) * S2;
            const float2* r1 = As2 + (kk + tig + 4) * S2;
            float2 a00 = r0[mi0],      a01 = r0[mi0 + 8];
            float2 a02 = r1[mi0],      a03 = r1[mi0 + 8];
            float2 a10 = r0[mi0 + 16], a11 = r0[mi0 + 24];
            float2 a12 = r1[mi0 + 16], a13 = r1[mi0 + 24];
            const float2* q0 = Bs2 + (kk + tig) * S2;
            const float2* q1 = Bs2 + (kk + tig + 4) * S2;
            #pragma unroll
            for (int nt = 0; nt < 8; nt++) {
                int nb = nb0 + nt * 8;
                float2 b0 = q0[nb], b1 = q1[nb];
                MMA_TF32(acc[0][nt], a00.y, a01.y, a02.y, a03.y, b0.x, b1.x);
                MMA_TF32(acc[0][nt], a00.x, a01.x, a02.x, a03.x, b0.y, b1.y);
                MMA_TF32(acc[0][nt], a00.x, a01.x, a02.x, a03.x, b0.x, b1.x);
                MMA_TF32(acc[1][nt], a10.y, a11.y, a12.y, a13.y, b0.x, b1.x);
                MMA_TF32(acc[1][nt], a10.x, a11.x, a12.x, a13.x, b0.y, b1.y);
                MMA_TF32(acc[1][nt], a10.x, a11.x, a12.x, a13.x, b0.x, b1.x);
            }
        }
        __syncthreads();
    }

    bool wantT = (sel && bx != by);
    float* T = (float*)dsm2;    // reuse slabs (all MMA reads done)
    float* drow = g_dist + (size_t)b * N1 * N2;
    #pragma unroll
    for (int mt = 0; mt < 2; mt++) {
        int mrow = wm2 * 32 + mt * 16 + gid;
        float ni0 = nAs[mrow], ni1 = nAs[mrow + 8];
        size_t ro0 = (size_t)(i0 + mrow) * N2 + j0;
        size_t ro1 = ro0 + (size_t)8 * N2;
        #pragma unroll
        for (int nt = 0; nt < 8; nt++) {
            int jc = wn2 * 64 + nt * 8 + tig * 2;
            float nj0 = nBs[jc], nj1 = nBs[jc + 1];
            float2 o0, o1;
            o0.x = fmaxf(ni0 - 2.f * acc[mt][nt][0] + nj0, 0.f);
            o0.y = fmaxf(ni0 - 2.f * acc[mt][nt][1] + nj1, 0.f);
            o1.x = fmaxf(ni1 - 2.f * acc[mt][nt][2] + nj0, 0.f);
            o1.y = fmaxf(ni1 - 2.f * acc[mt][nt][3] + nj1, 0.f);
            *(float2*)(drow + ro0 + jc) = o0;
            *(float2*)(drow + ro1 + jc) = o1;
            if (wantT) {
                T[mrow * TS + jc] = o0.x;
                T[mrow * TS + jc + 1] = o0.y;
                T[(mrow + 8) * TS + jc] = o1.x;
                T[(mrow + 8) * TS + jc + 1] = o1.y;
            }
        }
    }
    if (wantT) {
        __syncthreads();
        // transposed write: output row (j0+c), cols i0..i0+127
        for (int e = tid; e < 128 * 32; e += 256) {
            int r4 = e & 31, c = e >> 5;
            float4 v;
            v.x = T[(r4 * 4 + 0) * TS + c];
            v.y = T[(r4 * 4 + 1) * TS + c];
            v.z = T[(r4 * 4 + 2) * TS + c];
            v.w = T[(r4 * 4 + 3) * TS + c];
            *(float4*)(drow + (size_t)(j0 + c) * N2 + i0 + r4 * 4) = v;
        }
    }
}

// ---------------- top-K v5: 4 rows/block, 4 concurrent extraction warps ----------------
#define RPB 4
__global__ void __launch_bounds__(256) k_topk(int sel)
{
    __shared__ unsigned long long segmin[RPB][256];   // 8 KB
    int q0 = blockIdx.x * RPB;
    int* idxo = sel ? g_idx2 : g_idx1;
    int tid = threadIdx.x;

    #pragma unroll
    for (int rr = 0; rr < RPB; rr++) {
        const float* row = g_dist + (size_t)(q0 + rr) * N2;
        int basej = tid * 16;
        float mv = __int_as_float(0x7f7fffff);
        int mj = basej;
        #pragma unroll
        for (int i = 0; i < 4; i++) {
            float4 f = *(const float4*)(row + basej + i * 4);
            int j0 = basej + i * 4;
            if (f.x < mv) { mv = f.x; mj = j0 + 0; }
            if (f.y < mv) { mv = f.y; mj = j0 + 1; }
            if (f.z < mv) { mv = f.z; mj = j0 + 2; }
            if (f.w < mv) { mv = f.w; mj = j0 + 3; }
        }
        segmin[rr][tid] = ((unsigned long long)__float_as_uint(mv) << 32) | (unsigned)mj;
    }
    __syncthreads();

    int w = tid >> 5, lane = tid & 31;
    if (w < RPB) {
        int q = q0 + w;
        const float* row = g_dist + (size_t)q * N2;
        unsigned long long r[8];
        #pragma unroll
        for (int i = 0; i < 8; i++) r[i] = segmin[w][lane + 32 * i];
        int ex[KN];
        #pragma unroll
        for (int i = 0; i < KN; i++) ex[i] = -1;

        for (int k = 0; k < KN; k++) {
            unsigned long long m = r[0];
            #pragma unroll
            for (int i = 1; i < 8; i++) m = u64min(m, r[i]);
            #pragma unroll
            for (int o = 16; o; o >>= 1)
                m = u64min(m, __shfl_xor_sync(0xffffffffu, m, o));
            int j = (int)(unsigned)(m & 0xffffffffULL);
            #pragma unroll
            for (int i = 0; i < KN; i++) if (i == k) ex[i] = j;
            if (lane == 0) idxo[q * KN + k] = j;
            if (k == KN - 1) break;

            int seg = j >> 4;
            unsigned long long v = ~0ull;
            if (lane < 16) {
                int idx = seg * 16 + lane;
                float f = __ldg(row + idx);
                v = ((unsigned long long)__float_as_uint(f) << 32) | (unsigned)idx;
                #pragma unroll
                for (int i = 0; i < KN; i++)
                    if (i <= k && ex[i] == idx) v = ~0ull;
            }
            #pragma unroll
            for (int o = 8; o; o >>= 1)
                v = u64min(v, __shfl_xor_sync(0xffffffffu, v, o));
            unsigned long long vb = __shfl_sync(0xffffffffu, v, 0);
            int slot = seg >> 5, ln = seg & 31;
            #pragma unroll
            for (int i = 0; i < 8; i++)
                if (i == slot && lane == ln) r[i] = vb;
        }
    }
}

// ---------------- fused MLP on tensor cores (bf16 3-term split, m16n8k16) ----------------
#define TNP 8
#define SY 132
#define MX   0
#define MYO  (144 * SY)
#define MWC  (MYO + 128 * SY)
#define MB   (MWC + 24 * SY * 2)
#define MH2  (MB + 384)
#define MSW2 (MH2 + 1024)
#define MSB2 (MSW2 + 1024)
#define MIDX (MSB2 + 128)
#define MLP2_SMEM ((MIDX + 128) * 4)

__global__ void __launch_bounds__(512) k_mlp_tc(
    const float* __restrict__ b0g, const float* __restrict__ b1g,
    const float* __restrict__ b2g,
    const float* __restrict__ n1w0, const float* __restrict__ n1b0,
    const float* __restrict__ n1w1, const float* __restrict__ n1b1,
    const float* __restrict__ n1w2, const float* __restrict__ n1b2)
{
    extern __shared__ float sm[];
    float* Xbuf = sm + MX;
    float* Ybuf = sm + MYO;
    uint2* Wc = (uint2*)(sm + MWC);
    float* biasS = sm + MB;
    float* h2s = sm + MH2;
    float* sw2 = sm + MSW2;
    float* sb2 = sm + MSB2;
    int* idxs = (int*)(sm + MIDX);

    int tid = threadIdx.x;
    int warp = tid >> 5, lane = tid & 31;
    int gid = lane >> 2, tig = lane & 3;
    int wm = warp & 7, nh = warp >> 3;
    int mi = wm * 16 + gid;
    int base = blockIdx.x * TNP;

    if (tid < 128) {
        idxs[tid] = g_idx1[base * KN + tid];
        #pragma unroll
        for (int r = 0; r < 8; r++) sw2[tid + 128 * r] = n1w2[tid + 128 * r];
        sb2[tid] = n1b2[tid];
        biasS[tid] = b0g[tid];
        biasS[128 + tid] = b1g[tid];
        biasS[256 + tid] = b2g[tid];
    }
    __syncthreads();

    for (int e = tid; e < 144 * 128; e += 512) {
        int i = e >> 7, col = e & 127;
        int tn = col >> 4;
        int pt = base + tn;
        int b = pt >> 12;
        int j = idxs[col];
        float v;
        if (i < 64) v = g_p1T[(size_t)pt * DD + i];
        else if (i < 128) v = g_p2T[((size_t)b * N2 + j) * DD + (i - 64)];
        else if (i < 131) v = g_x2T[(b * N2 + j) * 3 + (i - 128)] - g_x1T[pt * 3 + (i - 128)];
        else v = 0.f;
        Xbuf[i * SY + col] = v;
    }
    __syncthreads();

    if (tid < 128) {
        int col = tid;
        float dx0 = Xbuf[128 * SY + col];
        float dx1 = Xbuf[129 * SY + col];
        float dx2 = Xbuf[130 * SY + col];
        float h[8];
        #pragma unroll
        for (int j = 0; j < 8; j++) {
            float s = n1w0[j * 3 + 0] * dx0 + n1w0[j * 3 + 1] * dx1 + n1w0[j * 3 + 2] * dx2 + n1b0[j];
            h[j] = fmaxf(s, 0.f);
        }
        #pragma unroll
        for (int j = 0; j < 8; j++) {
            float s = n1b1[j];
            #pragma unroll
            for (int m = 0; m < 8; m++) s += n1w1[j * 8 + m] * h[m];
            h2s[col * 8 + j] = fmaxf(s, 0.f);
        }
    }

    #pragma unroll 1
    for (int l = 0; l < 3; l++) {
        const int KPL = (l == 0) ? 72 : 64;
        const float* Xin = (l == 1) ? Ybuf : Xbuf;
        float* Yout = (l == 1) ? Xbuf : Ybuf;

        float acc[8][4];
        #pragma unroll
        for (int nti = 0; nti < 8; nti++) {
            int c0 = (nh * 8 + nti) * 8 + tig * 2;
            acc[nti][0] = biasS[l * 128 + c0];
            acc[nti][1] = biasS[l * 128 + c0 + 1];
            acc[nti][2] = acc[nti][0];
            acc[nti][3] = acc[nti][1];
        }

        for (int kbp = 0; kbp < KPL; kbp += 24) {
            int cs = (KPL - kbp < 24) ? (KPL - kbp) : 24;
            __syncthreads();
            for (int e = tid; e < cs * 128; e += 512) {
                int kl = e >> 7, c = e & 127;
                Wc[kl * SY + c] = g_wbf[l][kbp + kl][c];
            }
            __syncthreads();
            for (int pp = 0; pp < cs; pp += 8) {
                int kp0 = kbp + pp + tig;
                int kp1 = kp0 + 4;
                int r00 = 2 * kp0, r10 = 2 * kp1;
                float x00 = Xin[r00 * SY + mi];
                float x01 = Xin[(r00 + 1) * SY + mi];
                float x02 = Xin[r00 * SY + mi + 8];
                float x03 = Xin[(r00 + 1) * SY + mi + 8];
                float x10 = Xin[r10 * SY + mi];
                float x11 = Xin[(r10 + 1) * SY + mi];
                float x12 = Xin[r10 * SY + mi + 8];
                float x13 = Xin[(r10 + 1) * SY + mi + 8];
                float h00 = bf16_trunc(x00), h01 = bf16_trunc(x01);
                float h02 = bf16_trunc(x02), h03 = bf16_trunc(x03);
                float h10 = bf16_trunc(x10), h11 = bf16_trunc(x11);
                float h12 = bf16_trunc(x12), h13 = bf16_trunc(x13);
                unsigned a0h = packbf2(h00, h01), a1h = packbf2(h02, h03);
                unsigned a2h = packbf2(h10, h11), a3h = packbf2(h12, h13);
                unsigned a0l = packbf2(x00 - h00, x01 - h01);
                unsigned a1l = packbf2(x02 - h02, x03 - h03);
                unsigned a2l = packbf2(x10 - h10, x11 - h11);
                unsigned a3l = packbf2(x12 - h12, x13 - h13);
                const uint2* w0p = Wc + (pp + tig) * SY;
                const uint2* w1p = Wc + (pp + tig + 4) * SY;
                #pragma unroll
                for (int nti = 0; nti < 8; nti++) {
                    int nb = (nh * 8 + nti) * 8 + gid;
                    uint2 b0 = w0p[nb], b1 = w1p[nb];
                    MMA_BF16(acc[nti], a0l, a1l, a2l, a3l, b0.x, b1.x);
                    MMA_BF16(acc[nti], a0h, a1h, a2h, a3h, b0.y, b1.y);
                    MMA_BF16(acc[nti], a0h, a1h, a2h, a3h, b0.x, b1.x);
                }
            }
        }
        __syncthreads();
        #pragma unroll
        for (int nti = 0; nti < 8; nti++) {
            int c0 = (nh * 8 + nti) * 8 + tig * 2;
            Yout[c0 * SY + mi] = leakyf(acc[nti][0]);
            Yout[(c0 + 1) * SY + mi] = leakyf(acc[nti][1]);
            Yout[c0 * SY + mi + 8] = leakyf(acc[nti][2]);
            Yout[(c0 + 1) * SY + mi + 8] = leakyf(acc[nti][3]);
        }
    }
    __syncthreads();

    {
        int col = tid >> 2, cq = tid & 3;
        float hj[8];
        #pragma unroll
        for (int j = 0; j < 8; j++) hj[j] = h2s[col * 8 + j];
        #pragma unroll 4
        for (int cc = 0; cc < 32; cc++) {
            int c = cq * 32 + cc;
            float s = sb2[c];
            #pragma unroll
            for (int j = 0; j < 8; j++) s += sw2[c * 8 + j] * hj[j];
            Xbuf[col * SY + c] = fmaxf(s, 0.f);
        }
    }
    __syncthreads();

    for (int e = tid; e < 1024; e += 512) {
        int pt = e >> 7, c = e & 127;
        const float* yr = Ybuf + c * SY + pt * 16;
        const float* sc = Xbuf + (pt * 16) * SY + c;
        float a = 0.f;
        #pragma unroll
        for (int k = 0; k < 16; k++) a += sc[k * SY] * yr[k];
        g_p2p[(size_t)(base + pt) * CO + c] = a;
    }
}

// ---------------- patch aggregation ----------------
__global__ void __launch_bounds__(128) k_patch(
    const float* __restrict__ n2w0, const float* __restrict__ n2b0,
    const float* __restrict__ n2w1, const float* __restrict__ n2b1,
    const float* __restrict__ n2w2, const float* __restrict__ n2b2,
    float* __restrict__ out)
{
    __shared__ float h2s[16][8];
    __shared__ int js[16];
    int q = blockIdx.x;
    int b = q / N1, n = q % N1;
    int tid = threadIdx.x;
    if (tid < 16) {
        int j = g_idx2[q * KN + tid];
        js[tid] = j;
        float dx0 = g_x1T[(b * N1 + j) * 3 + 0] - g_x1T[q * 3 + 0];
        float dx1 = g_x1T[(b * N1 + j) * 3 + 1] - g_x1T[q * 3 + 1];
        float dx2 = g_x1T[(b * N1 + j) * 3 + 2] - g_x1T[q * 3 + 2];
        float h[8];
        #pragma unroll
        for (int jj = 0; jj < 8; jj++) {
            float s = n2w0[jj * 3 + 0] * dx0 + n2w0[jj * 3 + 1] * dx1 + n2w0[jj * 3 + 2] * dx2 + n2b0[jj];
            h[jj] = fmaxf(s, 0.f);
        }
        #pragma unroll
        for (int jj = 0; jj < 8; jj++) {
            float s = n2b1[jj];
            #pragma unroll
            for (int m = 0; m < 8; m++) s += n2w1[jj * 8 + m] * h[m];
            h2s[tid][jj] = fmaxf(s, 0.f);
        }
    }
    __syncthreads();
    int c = tid;
    float w2r[8];
    #pragma unroll
    for (int j = 0; j < 8; j++) w2r[j] = n2w2[c * 8 + j];
    float bc = n2b2[c];
    float acc = 0.f;
    #pragma unroll
    for (int k = 0; k < KN; k++) {
        float s = bc;
        #pragma unroll
        for (int j = 0; j < 8; j++) s += w2r[j] * h2s[k][j];
        s = fmaxf(s, 0.f);
        acc += s * g_p2p[((size_t)b * N1 + js[k]) * CO + c];
    }
    out[(size_t)b * CO * N1 + (size_t)c * N1 + n] = acc;
}

// ---------------- launch ----------------
extern "C" void kernel_launch(void* const* d_in, const int* in_sizes, int n_in,
                              void* d_out, int out_size)
{
    int s = (n_in >= 31) ? 0 : -2;
    const float* xyz1 = (const float*)d_in[0];
    const float* xyz2 = (const float*)d_in[1];
    const float* pts1 = (const float*)d_in[2];
    const float* pts2 = (const float*)d_in[3];
    const float* vel1 = (const float*)d_in[4];
    const float* fcc  = (const float*)d_in[8 + s];
    const float* fcv  = (const float*)d_in[9 + s];
    const float* wxyz = (const float*)d_in[10 + s];
    const float* wpts = (const float*)d_in[12 + s];
    const float* mw0 = (const float*)d_in[13 + s];
    const float* mb0 = (const float*)d_in[14 + s];
    const float* mw1 = (const float*)d_in[15 + s];
    const float* mb1 = (const float*)d_in[16 + s];
    const float* mw2 = (const float*)d_in[17 + s];
    const float* mb2 = (const float*)d_in[18 + s];
    const float* n1w0 = (const float*)d_in[19 + s];
    const float* n1b0 = (const float*)d_in[20 + s];
    const float* n2w0 = (const float*)d_in[21 + s];
    const float* n2b0 = (const float*)d_in[22 + s];
    const float* n1w1 = (const float*)d_in[23 + s];
    const float* n1b1 = (const float*)d_in[24 + s];
    const float* n2w1 = (const float*)d_in[25 + s];
    const float* n2b1 = (const float*)d_in[26 + s];
    const float* n1w2 = (const float*)d_in[27 + s];
    const float* n1b2 = (const float*)d_in[28 + s];
    const float* n2w2 = (const float*)d_in[29 + s];
    const float* n2b2 = (const float*)d_in[30 + s];

    float* out = (float*)d_out;
    const int patch_elems = BATCH * CO * N1;
    const int vw_elems = BATCH * N1 * 3;
    float* out_vw = (out_size >= patch_elems + vw_elems) ? (out + patch_elems) : nullptr;

    cudaFuncSetAttribute(k_mlp_tc, cudaFuncAttributeMaxDynamicSharedMemorySize, (int)MLP2_SMEM);
    cudaFuncSetAttribute(k_dist_tc, cudaFuncAttributeMaxDynamicSharedMemorySize, (int)DIST_SMEM);

    const int prep_total = 2 * BATCH * CP * N1 + 2 * BATCH * 3 * N1;
    dim3 gg(N2 / 128, N1 / 128, BATCH);
    dim3 gt(N1 / 32, 2 * BATCH * 2);

    k_rigid<<<(BATCH * N1 + 127) / 128, 128>>>(xyz1, vel1, fcc, fcv, out_vw);
    k_prep<<<(prep_total + 255) / 256, 256>>>(xyz1, xyz2, pts1, pts2, wxyz, wpts);
    k_normsComb<<<(BATCH * 4096 + 127) / 128, 128>>>();
    k_dist_tc<<<gg, 256, DIST_SMEM>>>(0);
    k_topk<<<BATCH * N1 / RPB, 256>>>(0);
    k_transp<<<gt, 256>>>(pts1, pts2);
    k_wprep<<<108, 256>>>(mw0, mw1, mw2);
    k_mlp_tc<<<(BATCH * N1) / TNP, 512, MLP2_SMEM>>>(mb0, mb1, mb2,
                                                     n1w0, n1b0, n1w1, n1b1, n1w2, n1b2);
    k_dist_tc<<<gg, 256, DIST_SMEM>>>(1);
    k_topk<<<BATCH * N1 / RPB, 256>>>(1);
    k_patch<<<BATCH * N1, 128>>>(n2w0, n2b0, n2w1, n2b1, n2w2, n2b2, out);
}